// round 1
// baseline (speedup 1.0000x reference)
#include <cuda_runtime.h>

// Problem constants
#define B_   2
#define T_   8
#define H_   128
#define W_   192
#define C_   96
#define MW_  8          // window edge (8x8)
#define NT_  64         // tokens per window / per temporal tile
#define NWH_ 16
#define NWW_ 24
#define SH_  4          // shift
#define PAD_ 97         // smem row pad (odd -> conflict-friendly)
#define EPS_ 1e-3f
#define SCALE_ 0.3535533905932738f   // 1/sqrt(8)

#define NTOTAL_ (B_*T_*H_*W_*C_)     // 37,748,736 floats

// scratch (spatial-attn output; temporal attn runs in-place on it)
__device__ float g_buf[NTOTAL_];

// ---------------------------------------------------------------------------
// Kernel 1: LN1 + shifted-window spatial MHA.  One block = one 8x8 window.
// ---------------------------------------------------------------------------
__global__ __launch_bounds__(256, 3) void k_spatial(
    const float* __restrict__ x,
    const float* __restrict__ g1, const float* __restrict__ b1,
    const float* __restrict__ Wq, const float* __restrict__ bq,
    const float* __restrict__ Wk, const float* __restrict__ bk,
    const float* __restrict__ Wv, const float* __restrict__ bv,
    const float* __restrict__ Wo, const float* __restrict__ bo)
{
    extern __shared__ float sm[];
    float* xn  = sm;                    // 64*97 normalized tokens
    float* qkv = xn + NT_*PAD_;         // 64*48  [tok][q0..15 k16..31 v32..47]
    float* Wc  = qkv + NT_*48;          // 96*48 combined qkv weights (reused as oT)
    float* WoS = Wc + C_*48;            // 16*96
    __shared__ float muS[NT_], rsS[NT_];
    __shared__ int   gofs[NT_];

    const int tid = threadIdx.x;
    const int blk = blockIdx.x;
    const int win = blk % (NWH_*NWW_);
    const int bt  = blk / (NWH_*NWW_);
    const int wh = win / NWW_, ww = win % NWW_;

    if (tid < NT_) {
        int i = tid >> 3, j = tid & 7;
        int h = (wh*MW_ + i + SH_) & (H_-1);
        int w = (ww*MW_ + j + SH_) % W_;
        gofs[tid] = ((bt*H_ + h)*W_ + w)*C_;
    }
    // stage weights
    #pragma unroll
    for (int r = 0; r < 18; ++r) {
        int idx = r*256 + tid;                 // < 4608
        int c = idx / 48, j = idx - c*48;
        int which = j >> 4, hk = j & 15;
        const float* Wm = (which==0) ? Wq : ((which==1) ? Wk : Wv);
        Wc[idx] = Wm[c*16 + hk];
    }
    #pragma unroll
    for (int r = 0; r < 6; ++r) WoS[r*256+tid] = Wo[r*256+tid];
    __syncthreads();

    // load window (gather with roll applied)
    #pragma unroll
    for (int r = 0; r < 24; ++r) {
        int idx = r*256 + tid;
        int n = idx / C_, c = idx - n*C_;
        xn[n*PAD_ + c] = x[gofs[n] + c];
    }
    __syncthreads();
    // LN stats (one token per thread, stride-97 -> conflict-free)
    if (tid < NT_) {
        const float* xr = xn + tid*PAD_;
        float s = 0.f;
        #pragma unroll
        for (int c = 0; c < C_; ++c) s += xr[c];
        float mu = s * (1.0f/C_);
        float v = 0.f;
        #pragma unroll
        for (int c = 0; c < C_; ++c) { float d = xr[c] - mu; v = fmaf(d, d, v); }
        muS[tid] = mu;
        rsS[tid] = rsqrtf(v*(1.0f/C_) + EPS_);
    }
    __syncthreads();
    #pragma unroll
    for (int r = 0; r < 24; ++r) {
        int idx = r*256 + tid;
        int n = idx / C_, c = idx - n*C_;
        xn[n*PAD_+c] = (xn[n*PAD_+c] - muS[n]) * rsS[n] * g1[c] + b1[c];
    }
    __syncthreads();

    // QKV micro-GEMM: 64x48 = (16x4 tokens) x (16x3 outs)
    {
        const int tx = tid & 15;   // out group
        const int ty = tid >> 4;   // token group
        float acc[4][3];
        #pragma unroll
        for (int tn = 0; tn < 3; ++tn) {
            int j = tx*3 + tn;
            int which = j >> 4, hk = j & 15;
            float bias = (which==0) ? bq[hk] : ((which==1) ? bk[hk] : bv[hk]);
            #pragma unroll
            for (int tm = 0; tm < 4; ++tm) acc[tm][tn] = bias;
        }
        #pragma unroll 4
        for (int c = 0; c < C_; ++c) {
            float a[4], w[3];
            #pragma unroll
            for (int tm = 0; tm < 4; ++tm) a[tm] = xn[(ty*4+tm)*PAD_ + c];
            #pragma unroll
            for (int tn = 0; tn < 3; ++tn) w[tn] = Wc[c*48 + tx*3 + tn];
            #pragma unroll
            for (int tm = 0; tm < 4; ++tm)
                #pragma unroll
                for (int tn = 0; tn < 3; ++tn)
                    acc[tm][tn] = fmaf(a[tm], w[tn], acc[tm][tn]);
        }
        #pragma unroll
        for (int tm = 0; tm < 4; ++tm)
            #pragma unroll
            for (int tn = 0; tn < 3; ++tn)
                qkv[(ty*4+tm)*48 + tx*3 + tn] = acc[tm][tn];
    }
    __syncthreads();

    // attention: 128 rows (head,query), online softmax in registers
    float* oT = Wc;   // reuse as [16 hk][64 tok]
    if (tid < 128) {
        const int hh = tid >> 6, n = tid & 63;
        float4 q0 = *(const float4*)(qkv + n*48 + hh*8);
        float4 q1 = *(const float4*)(qkv + n*48 + hh*8 + 4);
        q0.x *= SCALE_; q0.y *= SCALE_; q0.z *= SCALE_; q0.w *= SCALE_;
        q1.x *= SCALE_; q1.y *= SCALE_; q1.z *= SCALE_; q1.w *= SCALE_;
        float o[8] = {0.f,0.f,0.f,0.f,0.f,0.f,0.f,0.f};
        float mx = -1e30f, sum = 0.f;
        for (int m = 0; m < NT_; ++m) {
            const float4 k0 = *(const float4*)(qkv + m*48 + 16 + hh*8);
            const float4 k1 = *(const float4*)(qkv + m*48 + 20 + hh*8);
            float s = q0.x*k0.x + q0.y*k0.y + q0.z*k0.z + q0.w*k0.w
                    + q1.x*k1.x + q1.y*k1.y + q1.z*k1.z + q1.w*k1.w;
            float nm   = fmaxf(mx, s);
            float corr = __expf(mx - nm);
            float p    = __expf(s - nm);
            sum = fmaf(sum, corr, p);
            const float4 v0 = *(const float4*)(qkv + m*48 + 32 + hh*8);
            const float4 v1 = *(const float4*)(qkv + m*48 + 36 + hh*8);
            o[0] = fmaf(o[0], corr, p*v0.x);
            o[1] = fmaf(o[1], corr, p*v0.y);
            o[2] = fmaf(o[2], corr, p*v0.z);
            o[3] = fmaf(o[3], corr, p*v0.w);
            o[4] = fmaf(o[4], corr, p*v1.x);
            o[5] = fmaf(o[5], corr, p*v1.y);
            o[6] = fmaf(o[6], corr, p*v1.z);
            o[7] = fmaf(o[7], corr, p*v1.w);
            mx = nm;
        }
        float inv = 1.0f / sum;
        #pragma unroll
        for (int i = 0; i < 8; ++i) oT[(hh*8+i)*64 + n] = o[i]*inv;
    }
    __syncthreads();

    // output projection: 64x96 = (16x4 tokens) x (16x6 chans)
    {
        const int tx = tid & 15;   // chan group
        const int ty = tid >> 4;   // token group
        float acc[4][6];
        #pragma unroll
        for (int tn = 0; tn < 6; ++tn) {
            float bias = bo[tx*6+tn];
            #pragma unroll
            for (int tm = 0; tm < 4; ++tm) acc[tm][tn] = bias;
        }
        #pragma unroll
        for (int hk = 0; hk < 16; ++hk) {
            float4 av = *(const float4*)(oT + hk*64 + ty*4);
            float a[4] = {av.x, av.y, av.z, av.w};
            float w[6];
            #pragma unroll
            for (int tn = 0; tn < 6; ++tn) w[tn] = WoS[hk*96 + tx*6 + tn];
            #pragma unroll
            for (int tm = 0; tm < 4; ++tm)
                #pragma unroll
                for (int tn = 0; tn < 6; ++tn)
                    acc[tm][tn] = fmaf(a[tm], w[tn], acc[tm][tn]);
        }
        #pragma unroll
        for (int tm = 0; tm < 4; ++tm)
            #pragma unroll
            for (int tn = 0; tn < 6; ++tn)
                xn[(ty*4+tm)*PAD_ + tx*6 + tn] = acc[tm][tn];
    }
    __syncthreads();
    #pragma unroll
    for (int r = 0; r < 24; ++r) {
        int idx = r*256 + tid;
        int n = idx / C_, c = idx - n*C_;
        g_buf[gofs[n] + c] = xn[n*PAD_ + c];
    }
}

// ---------------------------------------------------------------------------
// Kernel 2: temporal MHA (in-place on g_buf). Block = (b,h, 8-wide w strip),
// 64 token slots = 8 positions x 8 timesteps.
// ---------------------------------------------------------------------------
__global__ __launch_bounds__(256, 3) void k_temporal(
    const float* __restrict__ Wq, const float* __restrict__ bq,
    const float* __restrict__ Wk, const float* __restrict__ bk,
    const float* __restrict__ Wv, const float* __restrict__ bv,
    const float* __restrict__ Wo, const float* __restrict__ bo)
{
    extern __shared__ float sm[];
    float* xin = sm;                    // 64*97  slot s = p*8 + t
    float* qkv = xin + NT_*PAD_;        // 64*48
    float* Wc  = qkv + NT_*48;          // 96*48 (reused as oT)
    float* WoS = Wc + C_*48;            // 16*96

    const int tid = threadIdx.x;
    const int blk = blockIdx.x;
    const int wp = blk % (W_/8);
    const int h  = (blk / (W_/8)) % H_;
    const int b  = blk / ((W_/8)*H_);
    const int w0 = wp*8;
    const int base0   = (((b*T_)*H_ + h)*W_ + w0)*C_;
    const int tstride = H_*W_*C_;

    #pragma unroll
    for (int r = 0; r < 18; ++r) {
        int idx = r*256 + tid;
        int c = idx / 48, j = idx - c*48;
        int which = j >> 4, hk = j & 15;
        const float* Wm = (which==0) ? Wq : ((which==1) ? Wk : Wv);
        Wc[idx] = Wm[c*16 + hk];
    }
    #pragma unroll
    for (int r = 0; r < 6; ++r) WoS[r*256+tid] = Wo[r*256+tid];

    // load tile: per t a contiguous 768-float chunk
    #pragma unroll
    for (int r = 0; r < 24; ++r) {
        int idx = r*256 + tid;                // 0..6143
        int t = idx / 768; int rem = idx - t*768;
        int p = rem / C_;  int c = rem - p*C_;
        xin[(p*8+t)*PAD_ + c] = g_buf[base0 + t*tstride + rem];
    }
    __syncthreads();

    // QKV micro-GEMM (same shape as kernel 1)
    {
        const int tx = tid & 15;
        const int ty = tid >> 4;
        float acc[4][3];
        #pragma unroll
        for (int tn = 0; tn < 3; ++tn) {
            int j = tx*3 + tn;
            int which = j >> 4, hk = j & 15;
            float bias = (which==0) ? bq[hk] : ((which==1) ? bk[hk] : bv[hk]);
            #pragma unroll
            for (int tm = 0; tm < 4; ++tm) acc[tm][tn] = bias;
        }
        #pragma unroll 4
        for (int c = 0; c < C_; ++c) {
            float a[4], w[3];
            #pragma unroll
            for (int tm = 0; tm < 4; ++tm) a[tm] = xin[(ty*4+tm)*PAD_ + c];
            #pragma unroll
            for (int tn = 0; tn < 3; ++tn) w[tn] = Wc[c*48 + tx*3 + tn];
            #pragma unroll
            for (int tm = 0; tm < 4; ++tm)
                #pragma unroll
                for (int tn = 0; tn < 3; ++tn)
                    acc[tm][tn] = fmaf(a[tm], w[tn], acc[tm][tn]);
        }
        #pragma unroll
        for (int tm = 0; tm < 4; ++tm)
            #pragma unroll
            for (int tn = 0; tn < 3; ++tn)
                qkv[(ty*4+tm)*48 + tx*3 + tn] = acc[tm][tn];
    }
    __syncthreads();

    // attention over T=8: 128 rows = 8 pos x 2 heads x 8 queries
    float* oT = Wc;
    if (tid < 128) {
        const int p  = tid >> 4;
        const int hh = (tid >> 3) & 1;
        const int n  = tid & 7;
        const int sb = p*8;
        float4 q0 = *(const float4*)(qkv + (sb+n)*48 + hh*8);
        float4 q1 = *(const float4*)(qkv + (sb+n)*48 + hh*8 + 4);
        q0.x *= SCALE_; q0.y *= SCALE_; q0.z *= SCALE_; q0.w *= SCALE_;
        q1.x *= SCALE_; q1.y *= SCALE_; q1.z *= SCALE_; q1.w *= SCALE_;
        float sc[8]; float mx = -1e30f;
        #pragma unroll
        for (int m = 0; m < 8; ++m) {
            const float4 k0 = *(const float4*)(qkv + (sb+m)*48 + 16 + hh*8);
            const float4 k1 = *(const float4*)(qkv + (sb+m)*48 + 20 + hh*8);
            float s = q0.x*k0.x + q0.y*k0.y + q0.z*k0.z + q0.w*k0.w
                    + q1.x*k1.x + q1.y*k1.y + q1.z*k1.z + q1.w*k1.w;
            sc[m] = s; mx = fmaxf(mx, s);
        }
        float sum = 0.f;
        #pragma unroll
        for (int m = 0; m < 8; ++m) { sc[m] = __expf(sc[m]-mx); sum += sc[m]; }
        float inv = 1.0f/sum;
        float o[8] = {0.f,0.f,0.f,0.f,0.f,0.f,0.f,0.f};
        #pragma unroll
        for (int m = 0; m < 8; ++m) {
            const float4 v0 = *(const float4*)(qkv + (sb+m)*48 + 32 + hh*8);
            const float4 v1 = *(const float4*)(qkv + (sb+m)*48 + 36 + hh*8);
            o[0] = fmaf(sc[m], v0.x, o[0]);
            o[1] = fmaf(sc[m], v0.y, o[1]);
            o[2] = fmaf(sc[m], v0.z, o[2]);
            o[3] = fmaf(sc[m], v0.w, o[3]);
            o[4] = fmaf(sc[m], v1.x, o[4]);
            o[5] = fmaf(sc[m], v1.y, o[5]);
            o[6] = fmaf(sc[m], v1.z, o[6]);
            o[7] = fmaf(sc[m], v1.w, o[7]);
        }
        #pragma unroll
        for (int i = 0; i < 8; ++i) oT[(hh*8+i)*64 + (sb+n)] = o[i]*inv;
    }
    __syncthreads();

    // output projection, stage into xin
    {
        const int tx = tid & 15;
        const int ty = tid >> 4;
        float acc[4][6];
        #pragma unroll
        for (int tn = 0; tn < 6; ++tn) {
            float bias = bo[tx*6+tn];
            #pragma unroll
            for (int tm = 0; tm < 4; ++tm) acc[tm][tn] = bias;
        }
        #pragma unroll
        for (int hk = 0; hk < 16; ++hk) {
            float4 av = *(const float4*)(oT + hk*64 + ty*4);
            float a[4] = {av.x, av.y, av.z, av.w};
            float w[6];
            #pragma unroll
            for (int tn = 0; tn < 6; ++tn) w[tn] = WoS[hk*96 + tx*6 + tn];
            #pragma unroll
            for (int tm = 0; tm < 4; ++tm)
                #pragma unroll
                for (int tn = 0; tn < 6; ++tn)
                    acc[tm][tn] = fmaf(a[tm], w[tn], acc[tm][tn]);
        }
        #pragma unroll
        for (int tm = 0; tm < 4; ++tm)
            #pragma unroll
            for (int tn = 0; tn < 6; ++tn)
                xin[(ty*4+tm)*PAD_ + tx*6 + tn] = acc[tm][tn];
    }
    __syncthreads();
    #pragma unroll
    for (int r = 0; r < 24; ++r) {
        int idx = r*256 + tid;
        int t = idx / 768; int rem = idx - t*768;
        int p = rem / C_;  int c = rem - p*C_;
        g_buf[base0 + t*tstride + rem] = xin[(p*8+t)*PAD_ + c];
    }
}

// ---------------------------------------------------------------------------
// Kernel 3: LN2 + MLP (96->96 relu, 96->96 relu). Block = 64 tokens.
// ---------------------------------------------------------------------------
__global__ __launch_bounds__(256, 2) void k_mlp(
    const float* __restrict__ g2, const float* __restrict__ b2,
    const float* __restrict__ W1, const float* __restrict__ b1m,
    const float* __restrict__ W2, const float* __restrict__ b2m,
    float* __restrict__ out)
{
    extern __shared__ float sm[];
    float* xn  = sm;              // 64*97
    float* hid = xn + NT_*PAD_;   // 64*97
    float* Ws  = hid + NT_*PAD_;  // 96*96
    __shared__ float muS[NT_], rsS[NT_];

    const int tid = threadIdx.x;
    const int gbase = blockIdx.x * NT_ * C_;

    #pragma unroll
    for (int r = 0; r < 24; ++r) {
        int idx = r*256 + tid;
        int n = idx / C_, c = idx - n*C_;
        xn[n*PAD_ + c] = g_buf[gbase + idx];
    }
    __syncthreads();
    if (tid < NT_) {
        const float* xr = xn + tid*PAD_;
        float s = 0.f;
        #pragma unroll
        for (int c = 0; c < C_; ++c) s += xr[c];
        float mu = s * (1.0f/C_);
        float v = 0.f;
        #pragma unroll
        for (int c = 0; c < C_; ++c) { float d = xr[c] - mu; v = fmaf(d, d, v); }
        muS[tid] = mu;
        rsS[tid] = rsqrtf(v*(1.0f/C_) + EPS_);
    }
    __syncthreads();
    #pragma unroll
    for (int r = 0; r < 24; ++r) {
        int idx = r*256 + tid;
        int n = idx / C_, c = idx - n*C_;
        xn[n*PAD_+c] = (xn[n*PAD_+c] - muS[n]) * rsS[n] * g2[c] + b2[c];
    }
    #pragma unroll
    for (int r = 0; r < 36; ++r) Ws[r*256+tid] = W1[r*256+tid];
    __syncthreads();

    const int tx = tid & 15;   // out group: c = tx*6..+5
    const int ty = tid >> 4;   // token group: n = ty*4..+3

    // GEMM1 + relu -> hid
    {
        float acc[4][6];
        #pragma unroll
        for (int tm = 0; tm < 4; ++tm)
            #pragma unroll
            for (int tn = 0; tn < 6; ++tn) acc[tm][tn] = 0.f;
        #pragma unroll 4
        for (int c = 0; c < C_; ++c) {
            float a[4], w[6];
            #pragma unroll
            for (int tm = 0; tm < 4; ++tm) a[tm] = xn[(ty*4+tm)*PAD_ + c];
            #pragma unroll
            for (int tn = 0; tn < 6; ++tn) w[tn] = Ws[c*C_ + tx*6 + tn];
            #pragma unroll
            for (int tm = 0; tm < 4; ++tm)
                #pragma unroll
                for (int tn = 0; tn < 6; ++tn)
                    acc[tm][tn] = fmaf(a[tm], w[tn], acc[tm][tn]);
        }
        #pragma unroll
        for (int tm = 0; tm < 4; ++tm)
            #pragma unroll
            for (int tn = 0; tn < 6; ++tn)
                hid[(ty*4+tm)*PAD_ + tx*6+tn] = fmaxf(acc[tm][tn] + b1m[tx*6+tn], 0.f);
    }
    __syncthreads();
    #pragma unroll
    for (int r = 0; r < 36; ++r) Ws[r*256+tid] = W2[r*256+tid];
    __syncthreads();

    // GEMM2 + relu -> stage into xn
    {
        float acc[4][6];
        #pragma unroll
        for (int tm = 0; tm < 4; ++tm)
            #pragma unroll
            for (int tn = 0; tn < 6; ++tn) acc[tm][tn] = 0.f;
        #pragma unroll 4
        for (int c = 0; c < C_; ++c) {
            float a[4], w[6];
            #pragma unroll
            for (int tm = 0; tm < 4; ++tm) a[tm] = hid[(ty*4+tm)*PAD_ + c];
            #pragma unroll
            for (int tn = 0; tn < 6; ++tn) w[tn] = Ws[c*C_ + tx*6 + tn];
            #pragma unroll
            for (int tm = 0; tm < 4; ++tm)
                #pragma unroll
                for (int tn = 0; tn < 6; ++tn)
                    acc[tm][tn] = fmaf(a[tm], w[tn], acc[tm][tn]);
        }
        #pragma unroll
        for (int tm = 0; tm < 4; ++tm)
            #pragma unroll
            for (int tn = 0; tn < 6; ++tn)
                xn[(ty*4+tm)*PAD_ + tx*6+tn] = fmaxf(acc[tm][tn] + b2m[tx*6+tn], 0.f);
    }
    __syncthreads();
    #pragma unroll
    for (int r = 0; r < 24; ++r) {
        int idx = r*256 + tid;
        int n = idx / C_, c = idx - n*C_;
        out[gbase + idx] = xn[n*PAD_ + c];
    }
}

// ---------------------------------------------------------------------------
extern "C" void kernel_launch(void* const* d_in, const int* in_sizes, int n_in,
                              void* d_out, int out_size)
{
    const float* x   = (const float*)d_in[0];
    const float* g1  = (const float*)d_in[1];
    const float* b1  = (const float*)d_in[2];
    const float* g2  = (const float*)d_in[3];
    const float* b2  = (const float*)d_in[4];
    const float* Wq  = (const float*)d_in[5];
    const float* bq  = (const float*)d_in[6];
    const float* Wk  = (const float*)d_in[7];
    const float* bk  = (const float*)d_in[8];
    const float* Wv  = (const float*)d_in[9];
    const float* bv  = (const float*)d_in[10];
    const float* Wo  = (const float*)d_in[11];
    const float* bo  = (const float*)d_in[12];
    const float* W1  = (const float*)d_in[13];
    const float* b1m = (const float*)d_in[14];
    const float* W2  = (const float*)d_in[15];
    const float* b2m = (const float*)d_in[16];
    float* out = (float*)d_out;

    const int smem12 = (NT_*PAD_ + NT_*48 + C_*48 + 16*C_) * sizeof(float);  // 61696
    const int smem3  = (2*NT_*PAD_ + C_*C_) * sizeof(float);                 // 86528

    cudaFuncSetAttribute(k_spatial,  cudaFuncAttributeMaxDynamicSharedMemorySize, smem12);
    cudaFuncSetAttribute(k_temporal, cudaFuncAttributeMaxDynamicSharedMemorySize, smem12);
    cudaFuncSetAttribute(k_mlp,      cudaFuncAttributeMaxDynamicSharedMemorySize, smem3);

    k_spatial<<<B_*T_*NWH_*NWW_, 256, smem12>>>(x, g1, b1, Wq, bq, Wk, bk, Wv, bv, Wo, bo);
    k_temporal<<<B_*H_*(W_/8), 256, smem12>>>(Wq, bq, Wk, bk, Wv, bv, Wo, bo);
    k_mlp<<<(B_*T_*H_*W_)/NT_, 256, smem3>>>(g2, b2, W1, b1m, W2, b2m, out);
}

// round 4
// speedup vs baseline: 1.1806x; 1.1806x over previous
#include <cuda_runtime.h>
#include <cuda_bf16.h>
#include <cstdint>

// Problem constants
#define B_   2
#define T_   8
#define H_   128
#define W_   192
#define C_   96
#define MW_  8          // window edge (8x8)
#define NT_  64         // tokens per window / per temporal tile
#define NWH_ 16
#define NWW_ 24
#define SH_  4          // shift
#define PAD_ 97         // smem row pad
#define EPS_ 1e-3f
#define SCALE_ 0.3535533905932738f   // 1/sqrt(8)

#define NTOTAL_ (B_*T_*H_*W_*C_)     // 37,748,736 floats

// scratch (spatial-attn output; temporal attn runs in-place on it)
__device__ float g_buf[NTOTAL_];

// ---------------------------------------------------------------------------
// Kernel 1: LN1 + shifted-window spatial MHA.  One block = one 8x8 window.
// (unchanged from round 1 — known good)
// ---------------------------------------------------------------------------
__global__ __launch_bounds__(256, 3) void k_spatial(
    const float* __restrict__ x,
    const float* __restrict__ g1, const float* __restrict__ b1,
    const float* __restrict__ Wq, const float* __restrict__ bq,
    const float* __restrict__ Wk, const float* __restrict__ bk,
    const float* __restrict__ Wv, const float* __restrict__ bv,
    const float* __restrict__ Wo, const float* __restrict__ bo)
{
    extern __shared__ float sm[];
    float* xn  = sm;                    // 64*97 normalized tokens
    float* qkv = xn + NT_*PAD_;         // 64*48
    float* Wc  = qkv + NT_*48;          // 96*48 combined qkv weights (reused as oT)
    float* WoS = Wc + C_*48;            // 16*96
    __shared__ float muS[NT_], rsS[NT_];
    __shared__ int   gofs[NT_];

    const int tid = threadIdx.x;
    const int blk = blockIdx.x;
    const int win = blk % (NWH_*NWW_);
    const int bt  = blk / (NWH_*NWW_);
    const int wh = win / NWW_, ww = win % NWW_;

    if (tid < NT_) {
        int i = tid >> 3, j = tid & 7;
        int h = (wh*MW_ + i + SH_) & (H_-1);
        int w = (ww*MW_ + j + SH_) % W_;
        gofs[tid] = ((bt*H_ + h)*W_ + w)*C_;
    }
    #pragma unroll
    for (int r = 0; r < 18; ++r) {
        int idx = r*256 + tid;
        int c = idx / 48, j = idx - c*48;
        int which = j >> 4, hk = j & 15;
        const float* Wm = (which==0) ? Wq : ((which==1) ? Wk : Wv);
        Wc[idx] = Wm[c*16 + hk];
    }
    #pragma unroll
    for (int r = 0; r < 6; ++r) WoS[r*256+tid] = Wo[r*256+tid];
    __syncthreads();

    #pragma unroll
    for (int r = 0; r < 24; ++r) {
        int idx = r*256 + tid;
        int n = idx / C_, c = idx - n*C_;
        xn[n*PAD_ + c] = x[gofs[n] + c];
    }
    __syncthreads();
    if (tid < NT_) {
        const float* xr = xn + tid*PAD_;
        float s = 0.f;
        #pragma unroll
        for (int c = 0; c < C_; ++c) s += xr[c];
        float mu = s * (1.0f/C_);
        float v = 0.f;
        #pragma unroll
        for (int c = 0; c < C_; ++c) { float d = xr[c] - mu; v = fmaf(d, d, v); }
        muS[tid] = mu;
        rsS[tid] = rsqrtf(v*(1.0f/C_) + EPS_);
    }
    __syncthreads();
    #pragma unroll
    for (int r = 0; r < 24; ++r) {
        int idx = r*256 + tid;
        int n = idx / C_, c = idx - n*C_;
        xn[n*PAD_+c] = (xn[n*PAD_+c] - muS[n]) * rsS[n] * g1[c] + b1[c];
    }
    __syncthreads();

    {
        const int tx = tid & 15;
        const int ty = tid >> 4;
        float acc[4][3];
        #pragma unroll
        for (int tn = 0; tn < 3; ++tn) {
            int j = tx*3 + tn;
            int which = j >> 4, hk = j & 15;
            float bias = (which==0) ? bq[hk] : ((which==1) ? bk[hk] : bv[hk]);
            #pragma unroll
            for (int tm = 0; tm < 4; ++tm) acc[tm][tn] = bias;
        }
        #pragma unroll 4
        for (int c = 0; c < C_; ++c) {
            float a[4], w[3];
            #pragma unroll
            for (int tm = 0; tm < 4; ++tm) a[tm] = xn[(ty*4+tm)*PAD_ + c];
            #pragma unroll
            for (int tn = 0; tn < 3; ++tn) w[tn] = Wc[c*48 + tx*3 + tn];
            #pragma unroll
            for (int tm = 0; tm < 4; ++tm)
                #pragma unroll
                for (int tn = 0; tn < 3; ++tn)
                    acc[tm][tn] = fmaf(a[tm], w[tn], acc[tm][tn]);
        }
        #pragma unroll
        for (int tm = 0; tm < 4; ++tm)
            #pragma unroll
            for (int tn = 0; tn < 3; ++tn)
                qkv[(ty*4+tm)*48 + tx*3 + tn] = acc[tm][tn];
    }
    __syncthreads();

    float* oT = Wc;
    if (tid < 128) {
        const int hh = tid >> 6, n = tid & 63;
        float4 q0 = *(const float4*)(qkv + n*48 + hh*8);
        float4 q1 = *(const float4*)(qkv + n*48 + hh*8 + 4);
        q0.x *= SCALE_; q0.y *= SCALE_; q0.z *= SCALE_; q0.w *= SCALE_;
        q1.x *= SCALE_; q1.y *= SCALE_; q1.z *= SCALE_; q1.w *= SCALE_;
        float o[8] = {0.f,0.f,0.f,0.f,0.f,0.f,0.f,0.f};
        float mx = -1e30f, sum = 0.f;
        for (int m = 0; m < NT_; ++m) {
            const float4 k0 = *(const float4*)(qkv + m*48 + 16 + hh*8);
            const float4 k1 = *(const float4*)(qkv + m*48 + 20 + hh*8);
            float s = q0.x*k0.x + q0.y*k0.y + q0.z*k0.z + q0.w*k0.w
                    + q1.x*k1.x + q1.y*k1.y + q1.z*k1.z + q1.w*k1.w;
            float nm   = fmaxf(mx, s);
            float corr = __expf(mx - nm);
            float p    = __expf(s - nm);
            sum = fmaf(sum, corr, p);
            const float4 v0 = *(const float4*)(qkv + m*48 + 32 + hh*8);
            const float4 v1 = *(const float4*)(qkv + m*48 + 36 + hh*8);
            o[0] = fmaf(o[0], corr, p*v0.x);
            o[1] = fmaf(o[1], corr, p*v0.y);
            o[2] = fmaf(o[2], corr, p*v0.z);
            o[3] = fmaf(o[3], corr, p*v0.w);
            o[4] = fmaf(o[4], corr, p*v1.x);
            o[5] = fmaf(o[5], corr, p*v1.y);
            o[6] = fmaf(o[6], corr, p*v1.z);
            o[7] = fmaf(o[7], corr, p*v1.w);
            mx = nm;
        }
        float inv = 1.0f / sum;
        #pragma unroll
        for (int i = 0; i < 8; ++i) oT[(hh*8+i)*64 + n] = o[i]*inv;
    }
    __syncthreads();

    {
        const int tx = tid & 15;
        const int ty = tid >> 4;
        float acc[4][6];
        #pragma unroll
        for (int tn = 0; tn < 6; ++tn) {
            float bias = bo[tx*6+tn];
            #pragma unroll
            for (int tm = 0; tm < 4; ++tm) acc[tm][tn] = bias;
        }
        #pragma unroll
        for (int hk = 0; hk < 16; ++hk) {
            float4 av = *(const float4*)(oT + hk*64 + ty*4);
            float a[4] = {av.x, av.y, av.z, av.w};
            float w[6];
            #pragma unroll
            for (int tn = 0; tn < 6; ++tn) w[tn] = WoS[hk*96 + tx*6 + tn];
            #pragma unroll
            for (int tm = 0; tm < 4; ++tm)
                #pragma unroll
                for (int tn = 0; tn < 6; ++tn)
                    acc[tm][tn] = fmaf(a[tm], w[tn], acc[tm][tn]);
        }
        #pragma unroll
        for (int tm = 0; tm < 4; ++tm)
            #pragma unroll
            for (int tn = 0; tn < 6; ++tn)
                xn[(ty*4+tm)*PAD_ + tx*6 + tn] = acc[tm][tn];
    }
    __syncthreads();
    #pragma unroll
    for (int r = 0; r < 24; ++r) {
        int idx = r*256 + tid;
        int n = idx / C_, c = idx - n*C_;
        g_buf[gofs[n] + c] = xn[n*PAD_ + c];
    }
}

// ---------------------------------------------------------------------------
// Kernel 2: temporal MHA (in-place on g_buf).  (unchanged from round 1)
// ---------------------------------------------------------------------------
__global__ __launch_bounds__(256, 3) void k_temporal(
    const float* __restrict__ Wq, const float* __restrict__ bq,
    const float* __restrict__ Wk, const float* __restrict__ bk,
    const float* __restrict__ Wv, const float* __restrict__ bv,
    const float* __restrict__ Wo, const float* __restrict__ bo)
{
    extern __shared__ float sm[];
    float* xin = sm;
    float* qkv = xin + NT_*PAD_;
    float* Wc  = qkv + NT_*48;
    float* WoS = Wc + C_*48;

    const int tid = threadIdx.x;
    const int blk = blockIdx.x;
    const int wp = blk % (W_/8);
    const int h  = (blk / (W_/8)) % H_;
    const int b  = blk / ((W_/8)*H_);
    const int w0 = wp*8;
    const int base0   = (((b*T_)*H_ + h)*W_ + w0)*C_;
    const int tstride = H_*W_*C_;

    #pragma unroll
    for (int r = 0; r < 18; ++r) {
        int idx = r*256 + tid;
        int c = idx / 48, j = idx - c*48;
        int which = j >> 4, hk = j & 15;
        const float* Wm = (which==0) ? Wq : ((which==1) ? Wk : Wv);
        Wc[idx] = Wm[c*16 + hk];
    }
    #pragma unroll
    for (int r = 0; r < 6; ++r) WoS[r*256+tid] = Wo[r*256+tid];

    #pragma unroll
    for (int r = 0; r < 24; ++r) {
        int idx = r*256 + tid;
        int t = idx / 768; int rem = idx - t*768;
        int p = rem / C_;  int c = rem - p*C_;
        xin[(p*8+t)*PAD_ + c] = g_buf[base0 + t*tstride + rem];
    }
    __syncthreads();

    {
        const int tx = tid & 15;
        const int ty = tid >> 4;
        float acc[4][3];
        #pragma unroll
        for (int tn = 0; tn < 3; ++tn) {
            int j = tx*3 + tn;
            int which = j >> 4, hk = j & 15;
            float bias = (which==0) ? bq[hk] : ((which==1) ? bk[hk] : bv[hk]);
            #pragma unroll
            for (int tm = 0; tm < 4; ++tm) acc[tm][tn] = bias;
        }
        #pragma unroll 4
        for (int c = 0; c < C_; ++c) {
            float a[4], w[3];
            #pragma unroll
            for (int tm = 0; tm < 4; ++tm) a[tm] = xin[(ty*4+tm)*PAD_ + c];
            #pragma unroll
            for (int tn = 0; tn < 3; ++tn) w[tn] = Wc[c*48 + tx*3 + tn];
            #pragma unroll
            for (int tm = 0; tm < 4; ++tm)
                #pragma unroll
                for (int tn = 0; tn < 3; ++tn)
                    acc[tm][tn] = fmaf(a[tm], w[tn], acc[tm][tn]);
        }
        #pragma unroll
        for (int tm = 0; tm < 4; ++tm)
            #pragma unroll
            for (int tn = 0; tn < 3; ++tn)
                qkv[(ty*4+tm)*48 + tx*3 + tn] = acc[tm][tn];
    }
    __syncthreads();

    float* oT = Wc;
    if (tid < 128) {
        const int p  = tid >> 4;
        const int hh = (tid >> 3) & 1;
        const int n  = tid & 7;
        const int sb = p*8;
        float4 q0 = *(const float4*)(qkv + (sb+n)*48 + hh*8);
        float4 q1 = *(const float4*)(qkv + (sb+n)*48 + hh*8 + 4);
        q0.x *= SCALE_; q0.y *= SCALE_; q0.z *= SCALE_; q0.w *= SCALE_;
        q1.x *= SCALE_; q1.y *= SCALE_; q1.z *= SCALE_; q1.w *= SCALE_;
        float sc[8]; float mx = -1e30f;
        #pragma unroll
        for (int m = 0; m < 8; ++m) {
            const float4 k0 = *(const float4*)(qkv + (sb+m)*48 + 16 + hh*8);
            const float4 k1 = *(const float4*)(qkv + (sb+m)*48 + 20 + hh*8);
            float s = q0.x*k0.x + q0.y*k0.y + q0.z*k0.z + q0.w*k0.w
                    + q1.x*k1.x + q1.y*k1.y + q1.z*k1.z + q1.w*k1.w;
            sc[m] = s; mx = fmaxf(mx, s);
        }
        float sum = 0.f;
        #pragma unroll
        for (int m = 0; m < 8; ++m) { sc[m] = __expf(sc[m]-mx); sum += sc[m]; }
        float inv = 1.0f/sum;
        float o[8] = {0.f,0.f,0.f,0.f,0.f,0.f,0.f,0.f};
        #pragma unroll
        for (int m = 0; m < 8; ++m) {
            const float4 v0 = *(const float4*)(qkv + (sb+m)*48 + 32 + hh*8);
            const float4 v1 = *(const float4*)(qkv + (sb+m)*48 + 36 + hh*8);
            o[0] = fmaf(sc[m], v0.x, o[0]);
            o[1] = fmaf(sc[m], v0.y, o[1]);
            o[2] = fmaf(sc[m], v0.z, o[2]);
            o[3] = fmaf(sc[m], v0.w, o[3]);
            o[4] = fmaf(sc[m], v1.x, o[4]);
            o[5] = fmaf(sc[m], v1.y, o[5]);
            o[6] = fmaf(sc[m], v1.z, o[6]);
            o[7] = fmaf(sc[m], v1.w, o[7]);
        }
        #pragma unroll
        for (int i = 0; i < 8; ++i) oT[(hh*8+i)*64 + (sb+n)] = o[i]*inv;
    }
    __syncthreads();

    {
        const int tx = tid & 15;
        const int ty = tid >> 4;
        float acc[4][6];
        #pragma unroll
        for (int tn = 0; tn < 6; ++tn) {
            float bias = bo[tx*6+tn];
            #pragma unroll
            for (int tm = 0; tm < 4; ++tm) acc[tm][tn] = bias;
        }
        #pragma unroll
        for (int hk = 0; hk < 16; ++hk) {
            float4 av = *(const float4*)(oT + hk*64 + ty*4);
            float a[4] = {av.x, av.y, av.z, av.w};
            float w[6];
            #pragma unroll
            for (int tn = 0; tn < 6; ++tn) w[tn] = WoS[hk*96 + tx*6 + tn];
            #pragma unroll
            for (int tm = 0; tm < 4; ++tm)
                #pragma unroll
                for (int tn = 0; tn < 6; ++tn)
                    acc[tm][tn] = fmaf(a[tm], w[tn], acc[tm][tn]);
        }
        #pragma unroll
        for (int tm = 0; tm < 4; ++tm)
            #pragma unroll
            for (int tn = 0; tn < 6; ++tn)
                xin[(ty*4+tm)*PAD_ + tx*6 + tn] = acc[tm][tn];
    }
    __syncthreads();
    #pragma unroll
    for (int r = 0; r < 24; ++r) {
        int idx = r*256 + tid;
        int t = idx / 768; int rem = idx - t*768;
        int p = rem / C_;  int c = rem - p*C_;
        g_buf[base0 + t*tstride + rem] = xin[(p*8+t)*PAD_ + c];
    }
}

// ===========================================================================
// mma.sync / ldmatrix helpers (baseline ISA, works on target sm_103)
// ===========================================================================
__device__ __forceinline__ uint32_t smem_u32(const void* p) {
    uint32_t a;
    asm("{ .reg .u64 tmp; cvta.to.shared.u64 tmp, %1; cvt.u32.u64 %0, tmp; }"
        : "=r"(a) : "l"(p));
    return a;
}
__device__ __forceinline__ void ldsm4(uint32_t* r, uint32_t addr) {
    asm volatile("ldmatrix.sync.aligned.m8n8.x4.shared.b16 {%0,%1,%2,%3}, [%4];"
        : "=r"(r[0]), "=r"(r[1]), "=r"(r[2]), "=r"(r[3]) : "r"(addr));
}
__device__ __forceinline__ void ldsm2(uint32_t* r, uint32_t addr) {
    asm volatile("ldmatrix.sync.aligned.m8n8.x2.shared.b16 {%0,%1}, [%2];"
        : "=r"(r[0]), "=r"(r[1]) : "r"(addr));
}
__device__ __forceinline__ void mma_bf16(float* d, const uint32_t* a, const uint32_t* b) {
    asm volatile(
        "mma.sync.aligned.m16n8k16.row.col.f32.bf16.bf16.f32 "
        "{%0,%1,%2,%3}, {%4,%5,%6,%7}, {%8,%9}, {%0,%1,%2,%3};"
        : "+f"(d[0]), "+f"(d[1]), "+f"(d[2]), "+f"(d[3])
        : "r"(a[0]), "r"(a[1]), "r"(a[2]), "r"(a[3]), "r"(b[0]), "r"(b[1]));
}
__device__ __forceinline__ void split_bf16(float v, __nv_bfloat16& hi, __nv_bfloat16& lo) {
    hi = __float2bfloat16(v);
    lo = __float2bfloat16(v - __bfloat162float(hi));
}

// bf16 row stride for MMA operand buffers (208 B rows; 16B chunks of 8
// consecutive rows land on distinct 128B quarters -> conflict-free ldmatrix)
#define AST 104

// smem byte offsets for k_mlp_mma
#define MO_AHI   0
#define MO_ALO   (MO_AHI + 128*AST*2)        // 26624
#define MO_WHI   (MO_ALO + 128*AST*2)        // 53248
#define MO_WLO   (MO_WHI + 96*AST*2)         // 73216
#define MO_BIAS  (MO_WLO + 96*AST*2)         // 93184
#define MO_TOTAL (MO_BIAS + 4*96*4)          // 94720

// shared 128x96 GEMM: D(acc) += Ahi*Whi + Ahi*Wlo + Alo*Whi
__device__ __forceinline__ void gemm_128x96(
    uint32_t aHi, uint32_t aLo, uint32_t bHi, uint32_t bLo,
    int wid, int lane, float acc[12][4])
{
    const uint32_t aoff = ((uint32_t)(wid*16 + (lane & 15)) * AST + ((lane & 16) ? 8u : 0u)) * 2u;
    const uint32_t boff = ((uint32_t)(lane & 7) * AST + ((lane & 8) ? 8u : 0u)) * 2u;
    #pragma unroll
    for (int kb = 0; kb < 6; ++kb) {
        uint32_t Ah[4], Al[4];
        ldsm4(Ah, aHi + aoff + kb*32u);
        ldsm4(Al, aLo + aoff + kb*32u);
        #pragma unroll
        for (int nt = 0; nt < 12; ++nt) {
            uint32_t Bh[2], Bl[2];
            uint32_t bb = boff + (uint32_t)(nt*8*AST*2) + kb*32u;
            ldsm2(Bh, bHi + bb);
            ldsm2(Bl, bLo + bb);
            mma_bf16(acc[nt], Ah, Bh);
            mma_bf16(acc[nt], Ah, Bl);
            mma_bf16(acc[nt], Al, Bh);
        }
    }
}

// ---------------------------------------------------------------------------
// Kernel 3: LN2 + MLP via mma.sync bf16 hi/lo (fp32-accurate).
// One CTA = 128 tokens, 8 warps; warp w owns tokens [16w,16w+16), all 96 cols.
// ---------------------------------------------------------------------------
__global__ __launch_bounds__(256, 2) void k_mlp_mma(
    const float* __restrict__ g2, const float* __restrict__ b2,
    const float* __restrict__ W1, const float* __restrict__ b1m,
    const float* __restrict__ W2, const float* __restrict__ b2m,
    float* __restrict__ out)
{
    extern __shared__ char smem[];
    const int tid  = threadIdx.x;
    const int wid  = tid >> 5;
    const int lane = tid & 31;
    const int gbase = blockIdx.x * 128 * C_;

    __nv_bfloat16* sAhi = (__nv_bfloat16*)(smem + MO_AHI);
    __nv_bfloat16* sAlo = (__nv_bfloat16*)(smem + MO_ALO);
    __nv_bfloat16* sWhi = (__nv_bfloat16*)(smem + MO_WHI);
    __nv_bfloat16* sWlo = (__nv_bfloat16*)(smem + MO_WLO);
    float* sG2  = (float*)(smem + MO_BIAS);
    float* sB2  = sG2 + 96;
    float* sB1M = sG2 + 192;
    float* sB2M = sG2 + 288;

    const uint32_t aHi = smem_u32(sAhi);
    const uint32_t aLo = smem_u32(sAlo);
    const uint32_t wHi = smem_u32(sWhi);
    const uint32_t wLo = smem_u32(sWlo);

    if (tid < 96) {
        sG2[tid]  = g2[tid];
        sB2[tid]  = b2[tid];
        sB1M[tid] = b1m[tid];
        sB2M[tid] = b2m[tid];
    }
    // stage W1 (transposed to [n][k], hi/lo split)
    #pragma unroll 4
    for (int i = tid; i < C_*C_; i += 256) {
        int k = i / C_, n = i - k*C_;
        __nv_bfloat16 hi, lo;
        split_bf16(W1[i], hi, lo);
        sWhi[n*AST + k] = hi;
        sWlo[n*AST + k] = lo;
    }

    // ---- LN2 + hi/lo split into A (warp handles 16 tokens) ----
    {
        const float* xin = g_buf + gbase;
        #pragma unroll
        for (int bb = 0; bb < 2; ++bb) {
            float v[8][3];
            #pragma unroll
            for (int i = 0; i < 8; ++i) {
                int tok = wid*16 + bb*8 + i;
                const float* row = xin + tok*C_ + lane;
                v[i][0] = row[0]; v[i][1] = row[32]; v[i][2] = row[64];
            }
            #pragma unroll
            for (int i = 0; i < 8; ++i) {
                int tok = wid*16 + bb*8 + i;
                float s = v[i][0] + v[i][1] + v[i][2];
                float q = v[i][0]*v[i][0];
                q = fmaf(v[i][1], v[i][1], q);
                q = fmaf(v[i][2], v[i][2], q);
                #pragma unroll
                for (int o = 16; o > 0; o >>= 1) {
                    s += __shfl_xor_sync(0xffffffffu, s, o);
                    q += __shfl_xor_sync(0xffffffffu, q, o);
                }
                float mu = s * (1.0f/C_);
                float var = q * (1.0f/C_) - mu*mu;
                float rs = rsqrtf(var + EPS_);
                #pragma unroll
                for (int j = 0; j < 3; ++j) {
                    int c = lane + 32*j;
                    float y = (v[i][j] - mu) * rs * sG2[c] + sB2[c];
                    __nv_bfloat16 hi, lo;
                    split_bf16(y, hi, lo);
                    sAhi[tok*AST + c] = hi;
                    sAlo[tok*AST + c] = lo;
                }
            }
        }
    }
    __syncthreads();

    const int r0  = wid*16 + (lane >> 2);
    const int cb0 = (lane & 3) * 2;

    // ---- GEMM1 ----
    float acc[12][4];
    #pragma unroll
    for (int nt = 0; nt < 12; ++nt)
        #pragma unroll
        for (int j = 0; j < 4; ++j) acc[nt][j] = 0.f;
    gemm_128x96(aHi, aLo, wHi, wLo, wid, lane, acc);
    __syncthreads();

    // ---- epilogue1: bias+relu, hi/lo re-split into A ----
    #pragma unroll
    for (int nt = 0; nt < 12; ++nt) {
        int col = nt*8 + cb0;
        float h00 = fmaxf(acc[nt][0] + sB1M[col],     0.f);
        float h01 = fmaxf(acc[nt][1] + sB1M[col + 1], 0.f);
        float h10 = fmaxf(acc[nt][2] + sB1M[col],     0.f);
        float h11 = fmaxf(acc[nt][3] + sB1M[col + 1], 0.f);
        __nv_bfloat16 hi, lo;
        split_bf16(h00, hi, lo); sAhi[r0*AST + col]       = hi; sAlo[r0*AST + col]       = lo;
        split_bf16(h01, hi, lo); sAhi[r0*AST + col + 1]   = hi; sAlo[r0*AST + col + 1]   = lo;
        split_bf16(h10, hi, lo); sAhi[(r0+8)*AST + col]   = hi; sAlo[(r0+8)*AST + col]   = lo;
        split_bf16(h11, hi, lo); sAhi[(r0+8)*AST + col+1] = hi; sAlo[(r0+8)*AST + col+1] = lo;
    }
    // stage W2
    #pragma unroll 4
    for (int i = tid; i < C_*C_; i += 256) {
        int k = i / C_, n = i - k*C_;
        __nv_bfloat16 hi, lo;
        split_bf16(W2[i], hi, lo);
        sWhi[n*AST + k] = hi;
        sWlo[n*AST + k] = lo;
    }
    __syncthreads();

    // ---- GEMM2 ----
    #pragma unroll
    for (int nt = 0; nt < 12; ++nt)
        #pragma unroll
        for (int j = 0; j < 4; ++j) acc[nt][j] = 0.f;
    gemm_128x96(aHi, aLo, wHi, wLo, wid, lane, acc);
    __syncthreads();   // before overwriting A region as staging

    // ---- epilogue2: bias+relu, stage f32 (stride 97) then coalesced store ----
    float* stg = (float*)(smem + MO_AHI);   // 128*97*4 = 49664 < 53248
    #pragma unroll
    for (int nt = 0; nt < 12; ++nt) {
        int col = nt*8 + cb0;
        stg[r0*97 + col]       = fmaxf(acc[nt][0] + sB2M[col],     0.f);
        stg[r0*97 + col + 1]   = fmaxf(acc[nt][1] + sB2M[col + 1], 0.f);
        stg[(r0+8)*97 + col]   = fmaxf(acc[nt][2] + sB2M[col],     0.f);
        stg[(r0+8)*97 + col+1] = fmaxf(acc[nt][3] + sB2M[col + 1], 0.f);
    }
    __syncthreads();
    #pragma unroll
    for (int i = 0; i < 48; ++i) {
        int idx = i*256 + tid;              // < 12288
        int tok = idx / C_, c = idx - tok*C_;
        out[gbase + idx] = stg[tok*97 + c];
    }
}

// ---------------------------------------------------------------------------
extern "C" void kernel_launch(void* const* d_in, const int* in_sizes, int n_in,
                              void* d_out, int out_size)
{
    const float* x   = (const float*)d_in[0];
    const float* g1  = (const float*)d_in[1];
    const float* b1  = (const float*)d_in[2];
    const float* g2  = (const float*)d_in[3];
    const float* b2  = (const float*)d_in[4];
    const float* Wq  = (const float*)d_in[5];
    const float* bq  = (const float*)d_in[6];
    const float* Wk  = (const float*)d_in[7];
    const float* bk  = (const float*)d_in[8];
    const float* Wv  = (const float*)d_in[9];
    const float* bv  = (const float*)d_in[10];
    const float* Wo  = (const float*)d_in[11];
    const float* bo  = (const float*)d_in[12];
    const float* W1  = (const float*)d_in[13];
    const float* b1m = (const float*)d_in[14];
    const float* W2  = (const float*)d_in[15];
    const float* b2m = (const float*)d_in[16];
    float* out = (float*)d_out;

    const int smem12 = (NT_*PAD_ + NT_*48 + C_*48 + 16*C_) * sizeof(float);  // 61696

    cudaFuncSetAttribute(k_spatial,  cudaFuncAttributeMaxDynamicSharedMemorySize, smem12);
    cudaFuncSetAttribute(k_temporal, cudaFuncAttributeMaxDynamicSharedMemorySize, smem12);
    cudaFuncSetAttribute(k_mlp_mma,  cudaFuncAttributeMaxDynamicSharedMemorySize, MO_TOTAL);

    k_spatial<<<B_*T_*NWH_*NWW_, 256, smem12>>>(x, g1, b1, Wq, bq, Wk, bk, Wv, bv, Wo, bo);
    k_temporal<<<B_*H_*(W_/8), 256, smem12>>>(Wq, bq, Wk, bk, Wv, bv, Wo, bo);
    k_mlp_mma<<<(B_*T_*H_*W_)/128, 256, MO_TOTAL>>>(g2, b2, W1, b1m, W2, b2m, out);
}

// round 5
// speedup vs baseline: 1.3548x; 1.1475x over previous
#include <cuda_runtime.h>
#include <cuda_bf16.h>
#include <cstdint>

// Problem constants
#define B_   2
#define T_   8
#define H_   128
#define W_   192
#define C_   96
#define MW_  8          // window edge (8x8)
#define NT_  64         // tokens per window / per temporal tile
#define NWH_ 16
#define NWW_ 24
#define SH_  4          // shift
#define PAD_ 100        // smem row pad (div by 4 -> float4-aligned rows)
#define EPS_ 1e-3f
#define SCALE_ 0.3535533905932738f   // 1/sqrt(8)

#define NTOTAL_ (B_*T_*H_*W_*C_)     // 37,748,736 floats

// scratch (spatial-attn output; temporal attn runs in-place on it)
__device__ float g_buf[NTOTAL_];

// ---------------------------------------------------------------------------
// Kernel 1: LN1 + shifted-window spatial MHA.  One block = one 8x8 window.
// ---------------------------------------------------------------------------
__global__ __launch_bounds__(256, 3) void k_spatial(
    const float* __restrict__ x,
    const float* __restrict__ g1, const float* __restrict__ b1,
    const float* __restrict__ Wq, const float* __restrict__ bq,
    const float* __restrict__ Wk, const float* __restrict__ bk,
    const float* __restrict__ Wv, const float* __restrict__ bv,
    const float* __restrict__ Wo, const float* __restrict__ bo)
{
    extern __shared__ float sm[];
    float* xn  = sm;                    // 64*100 normalized tokens
    float* qkv = xn + NT_*PAD_;         // 64*48  [tok][q0..15 k16..31 v32..47]
    float* Wt  = qkv + NT_*48;          // 48*100 transposed qkv weights [j][c] (reused as oT)
    float* WoS = Wt + 48*PAD_;          // 16*96
    __shared__ int gofs[NT_];

    const int tid  = threadIdx.x;
    const int wid  = tid >> 5;
    const int lane = tid & 31;
    const int blk = blockIdx.x;
    const int win = blk % (NWH_*NWW_);
    const int bt  = blk / (NWH_*NWW_);
    const int wh = win / NWW_, ww = win % NWW_;

    if (tid < NT_) {
        int i = tid >> 3, j = tid & 7;
        int h = (wh*MW_ + i + SH_) & (H_-1);
        int w = (ww*MW_ + j + SH_) % W_;
        gofs[tid] = ((bt*H_ + h)*W_ + w)*C_;
    }
    // stage transposed qkv weights: Wt[j][c], j = which*16 + hk
    #pragma unroll
    for (int r = 0; r < 18; ++r) {
        int idx = r*256 + tid;                 // < 4608
        int j = idx / 96, c = idx - j*96;
        int which = j >> 4, hk = j & 15;
        const float* Wm = (which==0) ? Wq : ((which==1) ? Wk : Wv);
        Wt[j*PAD_ + c] = Wm[c*16 + hk];
    }
    #pragma unroll
    for (int r = 0; r < 6; ++r) WoS[r*256+tid] = Wo[r*256+tid];
    __syncthreads();

    // ---- fused load + LN (warp per 8 tokens, shuffle reduction) ----
    {
        float v[8][3];
        #pragma unroll
        for (int i = 0; i < 8; ++i) {
            int tok = wid*8 + i;
            const float* row = x + gofs[tok] + lane;
            v[i][0] = row[0]; v[i][1] = row[32]; v[i][2] = row[64];
        }
        #pragma unroll
        for (int i = 0; i < 8; ++i) {
            int tok = wid*8 + i;
            float s = v[i][0] + v[i][1] + v[i][2];
            float q = v[i][0]*v[i][0];
            q = fmaf(v[i][1], v[i][1], q);
            q = fmaf(v[i][2], v[i][2], q);
            #pragma unroll
            for (int o = 16; o > 0; o >>= 1) {
                s += __shfl_xor_sync(0xffffffffu, s, o);
                q += __shfl_xor_sync(0xffffffffu, q, o);
            }
            float mu = s * (1.0f/C_);
            float var = q * (1.0f/C_) - mu*mu;
            float rs = rsqrtf(var + EPS_);
            #pragma unroll
            for (int j = 0; j < 3; ++j) {
                int c = lane + 32*j;
                xn[tok*PAD_ + c] = (v[i][j] - mu) * rs * __ldg(g1 + c) + __ldg(b1 + c);
            }
        }
    }
    __syncthreads();

    // ---- QKV micro-GEMM: (16x4 tokens) x (16x3 outs), float4 both operands ----
    {
        const int tx = tid & 15;   // out group
        const int ty = tid >> 4;   // token group
        float acc[4][3];
        #pragma unroll
        for (int tn = 0; tn < 3; ++tn) {
            int j = tx*3 + tn;
            int which = j >> 4, hk = j & 15;
            float bias = (which==0) ? bq[hk] : ((which==1) ? bk[hk] : bv[hk]);
            #pragma unroll
            for (int tm = 0; tm < 4; ++tm) acc[tm][tn] = bias;
        }
        #pragma unroll 6
        for (int c = 0; c < C_; c += 4) {
            float4 a[4], w[3];
            #pragma unroll
            for (int tm = 0; tm < 4; ++tm) a[tm] = *(const float4*)(xn + (ty*4+tm)*PAD_ + c);
            #pragma unroll
            for (int tn = 0; tn < 3; ++tn) w[tn] = *(const float4*)(Wt + (tx*3+tn)*PAD_ + c);
            #pragma unroll
            for (int tm = 0; tm < 4; ++tm)
                #pragma unroll
                for (int tn = 0; tn < 3; ++tn) {
                    acc[tm][tn] = fmaf(a[tm].x, w[tn].x, acc[tm][tn]);
                    acc[tm][tn] = fmaf(a[tm].y, w[tn].y, acc[tm][tn]);
                    acc[tm][tn] = fmaf(a[tm].z, w[tn].z, acc[tm][tn]);
                    acc[tm][tn] = fmaf(a[tm].w, w[tn].w, acc[tm][tn]);
                }
        }
        #pragma unroll
        for (int tm = 0; tm < 4; ++tm)
            #pragma unroll
            for (int tn = 0; tn < 3; ++tn)
                qkv[(ty*4+tm)*48 + tx*3 + tn] = acc[tm][tn];
    }
    __syncthreads();

    // ---- attention: 256 threads, 2 per (head,query) row, 32 keys each ----
    float* oT = Wt;   // reuse as [16 hk][64 tok]
    {
        const int row  = tid >> 1;          // 0..127
        const int half = tid & 1;
        const int hh = row >> 6, n = row & 63;
        float4 q0 = *(const float4*)(qkv + n*48 + hh*8);
        float4 q1 = *(const float4*)(qkv + n*48 + hh*8 + 4);
        q0.x *= SCALE_; q0.y *= SCALE_; q0.z *= SCALE_; q0.w *= SCALE_;
        q1.x *= SCALE_; q1.y *= SCALE_; q1.z *= SCALE_; q1.w *= SCALE_;
        float o[8] = {0.f,0.f,0.f,0.f,0.f,0.f,0.f,0.f};
        float mx = -1e30f, sum = 0.f;
        #pragma unroll 4
        for (int mm = 0; mm < 32; ++mm) {
            const int m = mm*2 + half;      // parity-interleaved -> conflict-free
            const float4 k0 = *(const float4*)(qkv + m*48 + 16 + hh*8);
            const float4 k1 = *(const float4*)(qkv + m*48 + 20 + hh*8);
            float s = q0.x*k0.x + q0.y*k0.y + q0.z*k0.z + q0.w*k0.w
                    + q1.x*k1.x + q1.y*k1.y + q1.z*k1.z + q1.w*k1.w;
            float nm   = fmaxf(mx, s);
            float corr = __expf(mx - nm);
            float p    = __expf(s - nm);
            sum = fmaf(sum, corr, p);
            const float4 v0 = *(const float4*)(qkv + m*48 + 32 + hh*8);
            const float4 v1 = *(const float4*)(qkv + m*48 + 36 + hh*8);
            o[0] = fmaf(o[0], corr, p*v0.x);
            o[1] = fmaf(o[1], corr, p*v0.y);
            o[2] = fmaf(o[2], corr, p*v0.z);
            o[3] = fmaf(o[3], corr, p*v0.w);
            o[4] = fmaf(o[4], corr, p*v1.x);
            o[5] = fmaf(o[5], corr, p*v1.y);
            o[6] = fmaf(o[6], corr, p*v1.z);
            o[7] = fmaf(o[7], corr, p*v1.w);
            mx = nm;
        }
        // pairwise combine (lanes 2r / 2r+1)
        float mxo  = __shfl_xor_sync(0xffffffffu, mx, 1);
        float sumo = __shfl_xor_sync(0xffffffffu, sum, 1);
        float nm = fmaxf(mx, mxo);
        float c1 = __expf(mx - nm), c2 = __expf(mxo - nm);
        float inv = 1.0f / (sum*c1 + sumo*c2);
        #pragma unroll
        for (int i = 0; i < 8; ++i) {
            float oo = __shfl_xor_sync(0xffffffffu, o[i], 1);
            o[i] = o[i]*c1 + oo*c2;
        }
        __syncthreads();   // qkv reads done; oT overwrites Wt region
        if (!half) {
            #pragma unroll
            for (int i = 0; i < 8; ++i) oT[(hh*8+i)*64 + n] = o[i]*inv;
        }
    }
    __syncthreads();

    // ---- output projection: (16x4 tokens) x (16x6 chans) ----
    {
        const int tx = tid & 15;   // chan group
        const int ty = tid >> 4;   // token group
        float acc[4][6];
        #pragma unroll
        for (int tn = 0; tn < 6; ++tn) {
            float bias = bo[tx*6+tn];
            #pragma unroll
            for (int tm = 0; tm < 4; ++tm) acc[tm][tn] = bias;
        }
        #pragma unroll
        for (int hk = 0; hk < 16; ++hk) {
            float4 av = *(const float4*)(oT + hk*64 + ty*4);
            float a[4] = {av.x, av.y, av.z, av.w};
            float w[6];
            #pragma unroll
            for (int tn = 0; tn < 6; ++tn) w[tn] = WoS[hk*96 + tx*6 + tn];
            #pragma unroll
            for (int tm = 0; tm < 4; ++tm)
                #pragma unroll
                for (int tn = 0; tn < 6; ++tn)
                    acc[tm][tn] = fmaf(a[tm], w[tn], acc[tm][tn]);
        }
        #pragma unroll
        for (int tm = 0; tm < 4; ++tm)
            #pragma unroll
            for (int tn = 0; tn < 6; ++tn)
                xn[(ty*4+tm)*PAD_ + tx*6 + tn] = acc[tm][tn];
    }
    __syncthreads();
    #pragma unroll
    for (int r = 0; r < 24; ++r) {
        int idx = r*256 + tid;
        int n = idx / C_, c = idx - n*C_;
        g_buf[gofs[n] + c] = xn[n*PAD_ + c];
    }
}

// ---------------------------------------------------------------------------
// Kernel 2: temporal MHA (in-place on g_buf). Block = (b,h, 8-wide w strip),
// 64 token slots = 8 positions x 8 timesteps.
// ---------------------------------------------------------------------------
__global__ __launch_bounds__(256, 3) void k_temporal(
    const float* __restrict__ Wq, const float* __restrict__ bq,
    const float* __restrict__ Wk, const float* __restrict__ bk,
    const float* __restrict__ Wv, const float* __restrict__ bv,
    const float* __restrict__ Wo, const float* __restrict__ bo)
{
    extern __shared__ float sm[];
    float* xin = sm;                    // 64*100  slot s = p*8 + t
    float* qkv = xin + NT_*PAD_;        // 64*48
    float* Wt  = qkv + NT_*48;          // 48*100 (reused as oT)
    float* WoS = Wt + 48*PAD_;          // 16*96

    const int tid = threadIdx.x;
    const int blk = blockIdx.x;
    const int wp = blk % (W_/8);
    const int h  = (blk / (W_/8)) % H_;
    const int b  = blk / ((W_/8)*H_);
    const int w0 = wp*8;
    const int base0   = (((b*T_)*H_ + h)*W_ + w0)*C_;
    const int tstride = H_*W_*C_;

    #pragma unroll
    for (int r = 0; r < 18; ++r) {
        int idx = r*256 + tid;
        int j = idx / 96, c = idx - j*96;
        int which = j >> 4, hk = j & 15;
        const float* Wm = (which==0) ? Wq : ((which==1) ? Wk : Wv);
        Wt[j*PAD_ + c] = Wm[c*16 + hk];
    }
    #pragma unroll
    for (int r = 0; r < 6; ++r) WoS[r*256+tid] = Wo[r*256+tid];

    // load tile: per t a contiguous 768-float chunk
    #pragma unroll
    for (int r = 0; r < 24; ++r) {
        int idx = r*256 + tid;                // 0..6143
        int t = idx / 768; int rem = idx - t*768;
        int p = rem / C_;  int c = rem - p*C_;
        xin[(p*8+t)*PAD_ + c] = g_buf[base0 + t*tstride + rem];
    }
    __syncthreads();

    // QKV micro-GEMM (float4 both operands)
    {
        const int tx = tid & 15;
        const int ty = tid >> 4;
        float acc[4][3];
        #pragma unroll
        for (int tn = 0; tn < 3; ++tn) {
            int j = tx*3 + tn;
            int which = j >> 4, hk = j & 15;
            float bias = (which==0) ? bq[hk] : ((which==1) ? bk[hk] : bv[hk]);
            #pragma unroll
            for (int tm = 0; tm < 4; ++tm) acc[tm][tn] = bias;
        }
        #pragma unroll 6
        for (int c = 0; c < C_; c += 4) {
            float4 a[4], w[3];
            #pragma unroll
            for (int tm = 0; tm < 4; ++tm) a[tm] = *(const float4*)(xin + (ty*4+tm)*PAD_ + c);
            #pragma unroll
            for (int tn = 0; tn < 3; ++tn) w[tn] = *(const float4*)(Wt + (tx*3+tn)*PAD_ + c);
            #pragma unroll
            for (int tm = 0; tm < 4; ++tm)
                #pragma unroll
                for (int tn = 0; tn < 3; ++tn) {
                    acc[tm][tn] = fmaf(a[tm].x, w[tn].x, acc[tm][tn]);
                    acc[tm][tn] = fmaf(a[tm].y, w[tn].y, acc[tm][tn]);
                    acc[tm][tn] = fmaf(a[tm].z, w[tn].z, acc[tm][tn]);
                    acc[tm][tn] = fmaf(a[tm].w, w[tn].w, acc[tm][tn]);
                }
        }
        #pragma unroll
        for (int tm = 0; tm < 4; ++tm)
            #pragma unroll
            for (int tn = 0; tn < 3; ++tn)
                qkv[(ty*4+tm)*48 + tx*3 + tn] = acc[tm][tn];
    }
    __syncthreads();

    // attention over T=8: 128 rows = 8 pos x 2 heads x 8 queries
    float* oT = Wt;
    if (tid < 128) {
        const int p  = tid >> 4;
        const int hh = (tid >> 3) & 1;
        const int n  = tid & 7;
        const int sb = p*8;
        float4 q0 = *(const float4*)(qkv + (sb+n)*48 + hh*8);
        float4 q1 = *(const float4*)(qkv + (sb+n)*48 + hh*8 + 4);
        q0.x *= SCALE_; q0.y *= SCALE_; q0.z *= SCALE_; q0.w *= SCALE_;
        q1.x *= SCALE_; q1.y *= SCALE_; q1.z *= SCALE_; q1.w *= SCALE_;
        float sc[8]; float mx = -1e30f;
        #pragma unroll
        for (int m = 0; m < 8; ++m) {
            const float4 k0 = *(const float4*)(qkv + (sb+m)*48 + 16 + hh*8);
            const float4 k1 = *(const float4*)(qkv + (sb+m)*48 + 20 + hh*8);
            float s = q0.x*k0.x + q0.y*k0.y + q0.z*k0.z + q0.w*k0.w
                    + q1.x*k1.x + q1.y*k1.y + q1.z*k1.z + q1.w*k1.w;
            sc[m] = s; mx = fmaxf(mx, s);
        }
        float sum = 0.f;
        #pragma unroll
        for (int m = 0; m < 8; ++m) { sc[m] = __expf(sc[m]-mx); sum += sc[m]; }
        float inv = 1.0f/sum;
        float o[8] = {0.f,0.f,0.f,0.f,0.f,0.f,0.f,0.f};
        #pragma unroll
        for (int m = 0; m < 8; ++m) {
            const float4 v0 = *(const float4*)(qkv + (sb+m)*48 + 32 + hh*8);
            const float4 v1 = *(const float4*)(qkv + (sb+m)*48 + 36 + hh*8);
            o[0] = fmaf(sc[m], v0.x, o[0]);
            o[1] = fmaf(sc[m], v0.y, o[1]);
            o[2] = fmaf(sc[m], v0.z, o[2]);
            o[3] = fmaf(sc[m], v0.w, o[3]);
            o[4] = fmaf(sc[m], v1.x, o[4]);
            o[5] = fmaf(sc[m], v1.y, o[5]);
            o[6] = fmaf(sc[m], v1.z, o[6]);
            o[7] = fmaf(sc[m], v1.w, o[7]);
        }
        __syncthreads();   // qkv reads done; oT overwrites Wt region
        #pragma unroll
        for (int i = 0; i < 8; ++i) oT[(hh*8+i)*64 + (sb+n)] = o[i]*inv;
    } else {
        __syncthreads();
    }
    __syncthreads();

    // output projection, stage into xin
    {
        const int tx = tid & 15;
        const int ty = tid >> 4;
        float acc[4][6];
        #pragma unroll
        for (int tn = 0; tn < 6; ++tn) {
            float bias = bo[tx*6+tn];
            #pragma unroll
            for (int tm = 0; tm < 4; ++tm) acc[tm][tn] = bias;
        }
        #pragma unroll
        for (int hk = 0; hk < 16; ++hk) {
            float4 av = *(const float4*)(oT + hk*64 + ty*4);
            float a[4] = {av.x, av.y, av.z, av.w};
            float w[6];
            #pragma unroll
            for (int tn = 0; tn < 6; ++tn) w[tn] = WoS[hk*96 + tx*6 + tn];
            #pragma unroll
            for (int tm = 0; tm < 4; ++tm)
                #pragma unroll
                for (int tn = 0; tn < 6; ++tn)
                    acc[tm][tn] = fmaf(a[tm], w[tn], acc[tm][tn]);
        }
        #pragma unroll
        for (int tm = 0; tm < 4; ++tm)
            #pragma unroll
            for (int tn = 0; tn < 6; ++tn)
                xin[(ty*4+tm)*PAD_ + tx*6 + tn] = acc[tm][tn];
    }
    __syncthreads();
    #pragma unroll
    for (int r = 0; r < 24; ++r) {
        int idx = r*256 + tid;
        int t = idx / 768; int rem = idx - t*768;
        int p = rem / C_;  int c = rem - p*C_;
        g_buf[base0 + t*tstride + rem] = xin[(p*8+t)*PAD_ + c];
    }
}

// ===========================================================================
// mma.sync / ldmatrix helpers (baseline ISA, works on target sm_103)
// ===========================================================================
__device__ __forceinline__ uint32_t smem_u32(const void* p) {
    uint32_t a;
    asm("{ .reg .u64 tmp; cvta.to.shared.u64 tmp, %1; cvt.u32.u64 %0, tmp; }"
        : "=r"(a) : "l"(p));
    return a;
}
__device__ __forceinline__ void ldsm4(uint32_t* r, uint32_t addr) {
    asm volatile("ldmatrix.sync.aligned.m8n8.x4.shared.b16 {%0,%1,%2,%3}, [%4];"
        : "=r"(r[0]), "=r"(r[1]), "=r"(r[2]), "=r"(r[3]) : "r"(addr));
}
__device__ __forceinline__ void ldsm2(uint32_t* r, uint32_t addr) {
    asm volatile("ldmatrix.sync.aligned.m8n8.x2.shared.b16 {%0,%1}, [%2];"
        : "=r"(r[0]), "=r"(r[1]) : "r"(addr));
}
__device__ __forceinline__ void mma_bf16(float* d, const uint32_t* a, const uint32_t* b) {
    asm volatile(
        "mma.sync.aligned.m16n8k16.row.col.f32.bf16.bf16.f32 "
        "{%0,%1,%2,%3}, {%4,%5,%6,%7}, {%8,%9}, {%0,%1,%2,%3};"
        : "+f"(d[0]), "+f"(d[1]), "+f"(d[2]), "+f"(d[3])
        : "r"(a[0]), "r"(a[1]), "r"(a[2]), "r"(a[3]), "r"(b[0]), "r"(b[1]));
}
__device__ __forceinline__ void split_bf16(float v, __nv_bfloat16& hi, __nv_bfloat16& lo) {
    hi = __float2bfloat16(v);
    lo = __float2bfloat16(v - __bfloat162float(hi));
}

// bf16 row stride for MMA operand buffers (208 B rows; 16B chunks of 8
// consecutive rows land on distinct 128B quarters -> conflict-free ldmatrix)
#define AST 104

// smem byte offsets for k_mlp_mma
#define MO_AHI   0
#define MO_ALO   (MO_AHI + 128*AST*2)        // 26624
#define MO_WHI   (MO_ALO + 128*AST*2)        // 53248
#define MO_WLO   (MO_WHI + 96*AST*2)         // 73216
#define MO_BIAS  (MO_WLO + 96*AST*2)         // 93184
#define MO_TOTAL (MO_BIAS + 4*96*4)          // 94720

// shared 128x96 GEMM: D(acc) += Ahi*Whi + Ahi*Wlo + Alo*Whi
__device__ __forceinline__ void gemm_128x96(
    uint32_t aHi, uint32_t aLo, uint32_t bHi, uint32_t bLo,
    int wid, int lane, float acc[12][4])
{
    const uint32_t aoff = ((uint32_t)(wid*16 + (lane & 15)) * AST + ((lane & 16) ? 8u : 0u)) * 2u;
    const uint32_t boff = ((uint32_t)(lane & 7) * AST + ((lane & 8) ? 8u : 0u)) * 2u;
    #pragma unroll
    for (int kb = 0; kb < 6; ++kb) {
        uint32_t Ah[4], Al[4];
        ldsm4(Ah, aHi + aoff + kb*32u);
        ldsm4(Al, aLo + aoff + kb*32u);
        #pragma unroll
        for (int nt = 0; nt < 12; ++nt) {
            uint32_t Bh[2], Bl[2];
            uint32_t bb = boff + (uint32_t)(nt*8*AST*2) + kb*32u;
            ldsm2(Bh, bHi + bb);
            ldsm2(Bl, bLo + bb);
            mma_bf16(acc[nt], Ah, Bh);
            mma_bf16(acc[nt], Ah, Bl);
            mma_bf16(acc[nt], Al, Bh);
        }
    }
}

// ---------------------------------------------------------------------------
// Kernel 3: LN2 + MLP via mma.sync bf16 hi/lo (fp32-accurate).
// One CTA = 128 tokens, 8 warps; warp w owns tokens [16w,16w+16), all 96 cols.
// ---------------------------------------------------------------------------
__global__ __launch_bounds__(256, 2) void k_mlp_mma(
    const float* __restrict__ g2, const float* __restrict__ b2,
    const float* __restrict__ W1, const float* __restrict__ b1m,
    const float* __restrict__ W2, const float* __restrict__ b2m,
    float* __restrict__ out)
{
    extern __shared__ char smem[];
    const int tid  = threadIdx.x;
    const int wid  = tid >> 5;
    const int lane = tid & 31;
    const int gbase = blockIdx.x * 128 * C_;

    __nv_bfloat16* sAhi = (__nv_bfloat16*)(smem + MO_AHI);
    __nv_bfloat16* sAlo = (__nv_bfloat16*)(smem + MO_ALO);
    __nv_bfloat16* sWhi = (__nv_bfloat16*)(smem + MO_WHI);
    __nv_bfloat16* sWlo = (__nv_bfloat16*)(smem + MO_WLO);
    float* sG2  = (float*)(smem + MO_BIAS);
    float* sB2  = sG2 + 96;
    float* sB1M = sG2 + 192;
    float* sB2M = sG2 + 288;

    const uint32_t aHi = smem_u32(sAhi);
    const uint32_t aLo = smem_u32(sAlo);
    const uint32_t wHi = smem_u32(sWhi);
    const uint32_t wLo = smem_u32(sWlo);

    if (tid < 96) {
        sG2[tid]  = g2[tid];
        sB2[tid]  = b2[tid];
        sB1M[tid] = b1m[tid];
        sB2M[tid] = b2m[tid];
    }
    // stage W1 (transposed to [n][k], hi/lo split)
    #pragma unroll 4
    for (int i = tid; i < C_*C_; i += 256) {
        int k = i / C_, n = i - k*C_;
        __nv_bfloat16 hi, lo;
        split_bf16(W1[i], hi, lo);
        sWhi[n*AST + k] = hi;
        sWlo[n*AST + k] = lo;
    }

    // ---- LN2 + hi/lo split into A (warp handles 16 tokens) ----
    {
        const float* xin = g_buf + gbase;
        #pragma unroll
        for (int bb = 0; bb < 2; ++bb) {
            float v[8][3];
            #pragma unroll
            for (int i = 0; i < 8; ++i) {
                int tok = wid*16 + bb*8 + i;
                const float* row = xin + tok*C_ + lane;
                v[i][0] = row[0]; v[i][1] = row[32]; v[i][2] = row[64];
            }
            #pragma unroll
            for (int i = 0; i < 8; ++i) {
                int tok = wid*16 + bb*8 + i;
                float s = v[i][0] + v[i][1] + v[i][2];
                float q = v[i][0]*v[i][0];
                q = fmaf(v[i][1], v[i][1], q);
                q = fmaf(v[i][2], v[i][2], q);
                #pragma unroll
                for (int o = 16; o > 0; o >>= 1) {
                    s += __shfl_xor_sync(0xffffffffu, s, o);
                    q += __shfl_xor_sync(0xffffffffu, q, o);
                }
                float mu = s * (1.0f/C_);
                float var = q * (1.0f/C_) - mu*mu;
                float rs = rsqrtf(var + EPS_);
                #pragma unroll
                for (int j = 0; j < 3; ++j) {
                    int c = lane + 32*j;
                    float y = (v[i][j] - mu) * rs * sG2[c] + sB2[c];
                    __nv_bfloat16 hi, lo;
                    split_bf16(y, hi, lo);
                    sAhi[tok*AST + c] = hi;
                    sAlo[tok*AST + c] = lo;
                }
            }
        }
    }
    __syncthreads();

    const int r0  = wid*16 + (lane >> 2);
    const int cb0 = (lane & 3) * 2;

    // ---- GEMM1 ----
    float acc[12][4];
    #pragma unroll
    for (int nt = 0; nt < 12; ++nt)
        #pragma unroll
        for (int j = 0; j < 4; ++j) acc[nt][j] = 0.f;
    gemm_128x96(aHi, aLo, wHi, wLo, wid, lane, acc);
    __syncthreads();

    // ---- epilogue1: bias+relu, hi/lo re-split into A ----
    #pragma unroll
    for (int nt = 0; nt < 12; ++nt) {
        int col = nt*8 + cb0;
        float h00 = fmaxf(acc[nt][0] + sB1M[col],     0.f);
        float h01 = fmaxf(acc[nt][1] + sB1M[col + 1], 0.f);
        float h10 = fmaxf(acc[nt][2] + sB1M[col],     0.f);
        float h11 = fmaxf(acc[nt][3] + sB1M[col + 1], 0.f);
        __nv_bfloat16 hi, lo;
        split_bf16(h00, hi, lo); sAhi[r0*AST + col]       = hi; sAlo[r0*AST + col]       = lo;
        split_bf16(h01, hi, lo); sAhi[r0*AST + col + 1]   = hi; sAlo[r0*AST + col + 1]   = lo;
        split_bf16(h10, hi, lo); sAhi[(r0+8)*AST + col]   = hi; sAlo[(r0+8)*AST + col]   = lo;
        split_bf16(h11, hi, lo); sAhi[(r0+8)*AST + col+1] = hi; sAlo[(r0+8)*AST + col+1] = lo;
    }
    // stage W2
    #pragma unroll 4
    for (int i = tid; i < C_*C_; i += 256) {
        int k = i / C_, n = i - k*C_;
        __nv_bfloat16 hi, lo;
        split_bf16(W2[i], hi, lo);
        sWhi[n*AST + k] = hi;
        sWlo[n*AST + k] = lo;
    }
    __syncthreads();

    // ---- GEMM2 ----
    #pragma unroll
    for (int nt = 0; nt < 12; ++nt)
        #pragma unroll
        for (int j = 0; j < 4; ++j) acc[nt][j] = 0.f;
    gemm_128x96(aHi, aLo, wHi, wLo, wid, lane, acc);
    __syncthreads();   // before overwriting A region as staging

    // ---- epilogue2: bias+relu, stage f32 (stride 97) then coalesced store ----
    float* stg = (float*)(smem + MO_AHI);   // 128*97*4 = 49664 < 53248
    #pragma unroll
    for (int nt = 0; nt < 12; ++nt) {
        int col = nt*8 + cb0;
        stg[r0*97 + col]       = fmaxf(acc[nt][0] + sB2M[col],     0.f);
        stg[r0*97 + col + 1]   = fmaxf(acc[nt][1] + sB2M[col + 1], 0.f);
        stg[(r0+8)*97 + col]   = fmaxf(acc[nt][2] + sB2M[col],     0.f);
        stg[(r0+8)*97 + col+1] = fmaxf(acc[nt][3] + sB2M[col + 1], 0.f);
    }
    __syncthreads();
    #pragma unroll
    for (int i = 0; i < 48; ++i) {
        int idx = i*256 + tid;              // < 12288
        int tok = idx / C_, c = idx - tok*C_;
        out[gbase + idx] = stg[tok*97 + c];
    }
}

// ---------------------------------------------------------------------------
extern "C" void kernel_launch(void* const* d_in, const int* in_sizes, int n_in,
                              void* d_out, int out_size)
{
    const float* x   = (const float*)d_in[0];
    const float* g1  = (const float*)d_in[1];
    const float* b1  = (const float*)d_in[2];
    const float* g2  = (const float*)d_in[3];
    const float* b2  = (const float*)d_in[4];
    const float* Wq  = (const float*)d_in[5];
    const float* bq  = (const float*)d_in[6];
    const float* Wk  = (const float*)d_in[7];
    const float* bk  = (const float*)d_in[8];
    const float* Wv  = (const float*)d_in[9];
    const float* bv  = (const float*)d_in[10];
    const float* Wo  = (const float*)d_in[11];
    const float* bo  = (const float*)d_in[12];
    const float* W1  = (const float*)d_in[13];
    const float* b1m = (const float*)d_in[14];
    const float* W2  = (const float*)d_in[15];
    const float* b2m = (const float*)d_in[16];
    float* out = (float*)d_out;

    const int smem12 = (NT_*PAD_ + NT_*48 + 48*PAD_ + 16*C_) * sizeof(float);  // 63232

    cudaFuncSetAttribute(k_spatial,  cudaFuncAttributeMaxDynamicSharedMemorySize, smem12);
    cudaFuncSetAttribute(k_temporal, cudaFuncAttributeMaxDynamicSharedMemorySize, smem12);
    cudaFuncSetAttribute(k_mlp_mma,  cudaFuncAttributeMaxDynamicSharedMemorySize, MO_TOTAL);

    k_spatial<<<B_*T_*NWH_*NWW_, 256, smem12>>>(x, g1, b1, Wq, bq, Wk, bk, Wv, bv, Wo, bo);
    k_temporal<<<B_*H_*(W_/8), 256, smem12>>>(Wq, bq, Wk, bk, Wv, bv, Wo, bo);
    k_mlp_mma<<<(B_*T_*H_*W_)/128, 256, MO_TOTAL>>>(g2, b2, W1, b1m, W2, b2m, out);
}

// round 8
// speedup vs baseline: 1.4706x; 1.0855x over previous
#include <cuda_runtime.h>
#include <cuda_bf16.h>
#include <cstdint>

// Problem constants
#define B_   2
#define T_   8
#define H_   128
#define W_   192
#define C_   96
#define MW_  8          // window edge (8x8)
#define NT_  64         // tokens per window / per temporal tile
#define NWH_ 16
#define NWW_ 24
#define SH_  4          // shift
#define PAD_ 100        // smem row pad (div by 4 -> float4-aligned rows)
#define EPS_ 1e-3f
#define SCALE_ 0.3535533905932738f   // 1/sqrt(8)

#define NTOTAL_ (B_*T_*H_*W_*C_)     // 37,748,736 floats

// scratch (spatial-attn output; temporal attn runs in-place on it)
__device__ float g_buf[NTOTAL_];

// ===========================================================================
// mma.sync / ldmatrix helpers (baseline ISA, works on target sm_103)
// ===========================================================================
__device__ __forceinline__ uint32_t smem_u32(const void* p) {
    uint32_t a;
    asm("{ .reg .u64 tmp; cvta.to.shared.u64 tmp, %1; cvt.u32.u64 %0, tmp; }"
        : "=r"(a) : "l"(p));
    return a;
}
__device__ __forceinline__ void ldsm4(uint32_t* r, uint32_t addr) {
    asm volatile("ldmatrix.sync.aligned.m8n8.x4.shared.b16 {%0,%1,%2,%3}, [%4];"
        : "=r"(r[0]), "=r"(r[1]), "=r"(r[2]), "=r"(r[3]) : "r"(addr));
}
__device__ __forceinline__ void ldsm2(uint32_t* r, uint32_t addr) {
    asm volatile("ldmatrix.sync.aligned.m8n8.x2.shared.b16 {%0,%1}, [%2];"
        : "=r"(r[0]), "=r"(r[1]) : "r"(addr));
}
__device__ __forceinline__ void mma_bf16(float* d, const uint32_t* a, const uint32_t* b) {
    asm volatile(
        "mma.sync.aligned.m16n8k16.row.col.f32.bf16.bf16.f32 "
        "{%0,%1,%2,%3}, {%4,%5,%6,%7}, {%8,%9}, {%0,%1,%2,%3};"
        : "+f"(d[0]), "+f"(d[1]), "+f"(d[2]), "+f"(d[3])
        : "r"(a[0]), "r"(a[1]), "r"(a[2]), "r"(a[3]), "r"(b[0]), "r"(b[1]));
}
__device__ __forceinline__ void split_bf16(float v, __nv_bfloat16& hi, __nv_bfloat16& lo) {
    hi = __float2bfloat16(v);
    lo = __float2bfloat16(v - __bfloat162float(hi));
}

// bf16 row strides (conflict-free for ldmatrix)
#define AST  104    // 208B rows
#define PAST 24     // 48B rows (K=16 operands)

// ---------------------------------------------------------------------------
// spatial kernel smem layout (bytes)
// ---------------------------------------------------------------------------
#define SP_A     0
#define SP_ALO   (SP_A + 128*AST*2)      // 26624
#define SP_W     (SP_ALO + 128*AST*2)    // 53248  (qkv W hi; later proj W hi)
#define SP_WLO   (SP_W + 48*AST*2)       // 63232
#define SP_QKV   (SP_W + 2*48*AST*2)     // 73216  fp32 [128][48]
#define SP_PA    (SP_QKV + 128*48*4)     // 97792  proj A hi
#define SP_PALO  (SP_PA + 128*PAST*2)    // 103936
#define SP_TOTAL (SP_PALO + 128*PAST*2)  // 110080
#define SP_PW    SP_W
#define SP_PWLO  (SP_W + 96*PAST*2)      // 57856

// ---------------------------------------------------------------------------
// Kernel 1: LN1 + shifted-window spatial MHA, tensor-core GEMMs.
// One CTA = TWO 8x8 windows (128 tokens), 256 threads (8 warps x 16 tokens).
// ---------------------------------------------------------------------------
__global__ __launch_bounds__(256, 2) void k_spatial_mma(
    const float* __restrict__ x,
    const float* __restrict__ g1, const float* __restrict__ b1,
    const float* __restrict__ Wq, const float* __restrict__ bq,
    const float* __restrict__ Wk, const float* __restrict__ bk,
    const float* __restrict__ Wv, const float* __restrict__ bv,
    const float* __restrict__ Wo, const float* __restrict__ bo)
{
    extern __shared__ char smem[];
    __shared__ int gofs[128];

    __nv_bfloat16* sAhi  = (__nv_bfloat16*)(smem + SP_A);
    __nv_bfloat16* sAlo  = (__nv_bfloat16*)(smem + SP_ALO);
    __nv_bfloat16* sWhi  = (__nv_bfloat16*)(smem + SP_W);
    __nv_bfloat16* sWlo  = (__nv_bfloat16*)(smem + SP_WLO);
    __nv_bfloat16* sPAhi = (__nv_bfloat16*)(smem + SP_PA);
    __nv_bfloat16* sPAlo = (__nv_bfloat16*)(smem + SP_PALO);
    __nv_bfloat16* sPWhi = (__nv_bfloat16*)(smem + SP_PW);
    __nv_bfloat16* sPWlo = (__nv_bfloat16*)(smem + SP_PWLO);
    float*         qkvF  = (float*)(smem + SP_QKV);

    const uint32_t aHi  = smem_u32(sAhi);
    const uint32_t aLo  = smem_u32(sAlo);
    const uint32_t wHi  = smem_u32(sWhi);
    const uint32_t wLo  = smem_u32(sWlo);
    const uint32_t paHi = smem_u32(sPAhi);
    const uint32_t paLo = smem_u32(sPAlo);
    const uint32_t pwHi = smem_u32(sPWhi);
    const uint32_t pwLo = smem_u32(sPWlo);

    const int tid  = threadIdx.x;
    const int wid  = tid >> 5;
    const int lane = tid & 31;
    const int blk  = blockIdx.x;
    const int bt   = blk / 192;        // (b,t)
    const int wp   = blk % 192;        // window pair

    // token -> gmem offset (roll applied); tokens 0..63 win0, 64..127 win1
    if (tid < 128) {
        int wsel = tid >> 6;
        int win  = wp*2 + wsel;
        int wh = win / NWW_, ww = win % NWW_;
        int i = (tid >> 3) & 7, j = tid & 7;
        int h = (wh*MW_ + i + SH_) & (H_-1);
        int w = (ww*MW_ + j + SH_) % W_;
        gofs[tid] = ((bt*H_ + h)*W_ + w)*C_;
    }
    // stage qkv weights transposed [j=out(48)][k=c(96)], hi/lo
    #pragma unroll
    for (int r = 0; r < 18; ++r) {
        int i = r*256 + tid;           // < 4608
        int j = i / 96, c = i - j*96;
        int which = j >> 4, hk = j & 15;
        const float* Wm = (which==0) ? Wq : ((which==1) ? Wk : Wv);
        __nv_bfloat16 hi, lo;
        split_bf16(Wm[c*16 + hk], hi, lo);
        sWhi[j*AST + c] = hi;
        sWlo[j*AST + c] = lo;
    }
    __syncthreads();

    // ---- LN1 -> A hi/lo (warp handles 16 tokens) ----
    {
        #pragma unroll
        for (int bb = 0; bb < 2; ++bb) {
            float v[8][3];
            #pragma unroll
            for (int i = 0; i < 8; ++i) {
                int tok = wid*16 + bb*8 + i;
                const float* row = x + gofs[tok] + lane;
                v[i][0] = row[0]; v[i][1] = row[32]; v[i][2] = row[64];
            }
            #pragma unroll
            for (int i = 0; i < 8; ++i) {
                int tok = wid*16 + bb*8 + i;
                float s = v[i][0] + v[i][1] + v[i][2];
                float q = v[i][0]*v[i][0];
                q = fmaf(v[i][1], v[i][1], q);
                q = fmaf(v[i][2], v[i][2], q);
                #pragma unroll
                for (int o = 16; o > 0; o >>= 1) {
                    s += __shfl_xor_sync(0xffffffffu, s, o);
                    q += __shfl_xor_sync(0xffffffffu, q, o);
                }
                float mu = s * (1.0f/C_);
                float var = q * (1.0f/C_) - mu*mu;
                float rs = rsqrtf(var + EPS_);
                #pragma unroll
                for (int j = 0; j < 3; ++j) {
                    int c = lane + 32*j;
                    float y = (v[i][j] - mu) * rs * __ldg(g1+c) + __ldg(b1+c);
                    __nv_bfloat16 hi, lo;
                    split_bf16(y, hi, lo);
                    sAhi[tok*AST + c] = hi;
                    sAlo[tok*AST + c] = lo;
                }
            }
        }
    }
    __syncthreads();

    const int r0  = wid*16 + (lane >> 2);
    const int cb0 = (lane & 3) * 2;

    // ---- QKV GEMM: [128x96] x [96x48], 3-term hi/lo ----
    {
        float acc[6][4];
        #pragma unroll
        for (int nt = 0; nt < 6; ++nt)
            #pragma unroll
            for (int j = 0; j < 4; ++j) acc[nt][j] = 0.f;

        const uint32_t aoff = ((uint32_t)(wid*16 + (lane & 15)) * AST + ((lane & 16) ? 8u : 0u)) * 2u;
        const uint32_t boff = ((uint32_t)(lane & 7) * AST + ((lane & 8) ? 8u : 0u)) * 2u;
        #pragma unroll
        for (int kb = 0; kb < 6; ++kb) {
            uint32_t Ah[4], Al[4];
            ldsm4(Ah, aHi + aoff + kb*32u);
            ldsm4(Al, aLo + aoff + kb*32u);
            #pragma unroll
            for (int nt = 0; nt < 6; ++nt) {
                uint32_t Bh[2], Bl[2];
                uint32_t bb = boff + (uint32_t)(nt*8*AST*2) + kb*32u;
                ldsm2(Bh, wHi + bb);
                ldsm2(Bl, wLo + bb);
                mma_bf16(acc[nt], Ah, Bh);
                mma_bf16(acc[nt], Ah, Bl);
                mma_bf16(acc[nt], Al, Bh);
            }
        }
        // epilogue: bias, pre-scale q, store fp32
        #pragma unroll
        for (int nt = 0; nt < 6; ++nt) {
            int j0 = nt*8 + cb0;
            float bb0, bb1;
            if (j0 < 16)      { bb0 = __ldg(bq+j0);    bb1 = __ldg(bq+j0+1); }
            else if (j0 < 32) { bb0 = __ldg(bk+j0-16); bb1 = __ldg(bk+j0-15); }
            else              { bb0 = __ldg(bv+j0-32); bb1 = __ldg(bv+j0-31); }
            float scl = (j0 < 16) ? SCALE_ : 1.0f;
            qkvF[r0*48 + j0]       = (acc[nt][0] + bb0) * scl;
            qkvF[r0*48 + j0 + 1]   = (acc[nt][1] + bb1) * scl;
            qkvF[(r0+8)*48 + j0]   = (acc[nt][2] + bb0) * scl;
            qkvF[(r0+8)*48 + j0+1] = (acc[nt][3] + bb1) * scl;
        }
    }
    __syncthreads();

    // ---- attention: thread = (query pair, key half); 2 rows x 32 keys ----
    {
        const int t2   = tid >> 1;          // 0..127
        const int half = tid & 1;
        const int win  = t2 >> 6;
        const int rem  = t2 & 63;
        const int hh   = rem >> 5;
        const int np   = rem & 31;
        const int n0 = np*2, n1 = n0 + 1;
        const float* qb = qkvF + win*64*48;

        float4 qa0 = *(const float4*)(qb + n0*48 + hh*8);
        float4 qa1 = *(const float4*)(qb + n0*48 + hh*8 + 4);
        float4 qb0 = *(const float4*)(qb + n1*48 + hh*8);
        float4 qb1 = *(const float4*)(qb + n1*48 + hh*8 + 4);

        float oA[8] = {0,0,0,0,0,0,0,0}, oB[8] = {0,0,0,0,0,0,0,0};
        float mxA = -1e30f, sumA = 0.f, mxB = -1e30f, sumB = 0.f;

        #pragma unroll 4
        for (int mm = 0; mm < 32; ++mm) {
            const int m = mm*2 + half;
            const float4 k0 = *(const float4*)(qb + m*48 + 16 + hh*8);
            const float4 k1 = *(const float4*)(qb + m*48 + 20 + hh*8);
            const float4 v0 = *(const float4*)(qb + m*48 + 32 + hh*8);
            const float4 v1 = *(const float4*)(qb + m*48 + 36 + hh*8);
            float sA = qa0.x*k0.x + qa0.y*k0.y + qa0.z*k0.z + qa0.w*k0.w
                     + qa1.x*k1.x + qa1.y*k1.y + qa1.z*k1.z + qa1.w*k1.w;
            float sB = qb0.x*k0.x + qb0.y*k0.y + qb0.z*k0.z + qb0.w*k0.w
                     + qb1.x*k1.x + qb1.y*k1.y + qb1.z*k1.z + qb1.w*k1.w;
            float nmA = fmaxf(mxA, sA);
            float cA  = __expf(mxA - nmA);
            float pA  = __expf(sA - nmA);
            sumA = fmaf(sumA, cA, pA);
            float nmB = fmaxf(mxB, sB);
            float cB  = __expf(mxB - nmB);
            float pB  = __expf(sB - nmB);
            sumB = fmaf(sumB, cB, pB);
            oA[0] = fmaf(oA[0], cA, pA*v0.x);  oB[0] = fmaf(oB[0], cB, pB*v0.x);
            oA[1] = fmaf(oA[1], cA, pA*v0.y);  oB[1] = fmaf(oB[1], cB, pB*v0.y);
            oA[2] = fmaf(oA[2], cA, pA*v0.z);  oB[2] = fmaf(oB[2], cB, pB*v0.z);
            oA[3] = fmaf(oA[3], cA, pA*v0.w);  oB[3] = fmaf(oB[3], cB, pB*v0.w);
            oA[4] = fmaf(oA[4], cA, pA*v1.x);  oB[4] = fmaf(oB[4], cB, pB*v1.x);
            oA[5] = fmaf(oA[5], cA, pA*v1.y);  oB[5] = fmaf(oB[5], cB, pB*v1.y);
            oA[6] = fmaf(oA[6], cA, pA*v1.z);  oB[6] = fmaf(oB[6], cB, pB*v1.z);
            oA[7] = fmaf(oA[7], cA, pA*v1.w);  oB[7] = fmaf(oB[7], cB, pB*v1.w);
            mxA = nmA; mxB = nmB;
        }
        // combine the two key-halves (lanes 2r / 2r+1)
        {
            float mo = __shfl_xor_sync(0xffffffffu, mxA, 1);
            float so = __shfl_xor_sync(0xffffffffu, sumA, 1);
            float nm = fmaxf(mxA, mo);
            float c1 = __expf(mxA - nm), c2 = __expf(mo - nm);
            sumA = sumA*c1 + so*c2;
            #pragma unroll
            for (int i = 0; i < 8; ++i) {
                float oo = __shfl_xor_sync(0xffffffffu, oA[i], 1);
                oA[i] = oA[i]*c1 + oo*c2;
            }
        }
        {
            float mo = __shfl_xor_sync(0xffffffffu, mxB, 1);
            float so = __shfl_xor_sync(0xffffffffu, sumB, 1);
            float nm = fmaxf(mxB, mo);
            float c1 = __expf(mxB - nm), c2 = __expf(mo - nm);
            sumB = sumB*c1 + so*c2;
            #pragma unroll
            for (int i = 0; i < 8; ++i) {
                float oo = __shfl_xor_sync(0xffffffffu, oB[i], 1);
                oB[i] = oB[i]*c1 + oo*c2;
            }
        }
        // writer: half 0 -> row n0, half 1 -> row n1  (proj A layout [tok][hk])
        if (!half) {
            float inv = 1.0f / sumA;
            int tokp = win*64 + n0;
            #pragma unroll
            for (int i = 0; i < 8; ++i) {
                __nv_bfloat16 hi, lo;
                split_bf16(oA[i]*inv, hi, lo);
                sPAhi[tokp*PAST + hh*8 + i] = hi;
                sPAlo[tokp*PAST + hh*8 + i] = lo;
            }
        } else {
            float inv = 1.0f / sumB;
            int tokp = win*64 + n1;
            #pragma unroll
            for (int i = 0; i < 8; ++i) {
                __nv_bfloat16 hi, lo;
                split_bf16(oB[i]*inv, hi, lo);
                sPAhi[tokp*PAST + hh*8 + i] = hi;
                sPAlo[tokp*PAST + hh*8 + i] = lo;
            }
        }
    }
    __syncthreads();

    // stage proj weights [n=c(96)][k=hk(16)] hi/lo (reuses qkv W region)
    #pragma unroll
    for (int r = 0; r < 6; ++r) {
        int i = r*256 + tid;               // < 1536
        int c = i >> 4, hk = i & 15;
        __nv_bfloat16 hi, lo;
        split_bf16(Wo[hk*96 + c], hi, lo);
        sPWhi[c*PAST + hk] = hi;
        sPWlo[c*PAST + hk] = lo;
    }
    __syncthreads();

    // ---- projection GEMM: [128x16] x [16x96] ----
    {
        float acc[12][4];
        #pragma unroll
        for (int nt = 0; nt < 12; ++nt)
            #pragma unroll
            for (int j = 0; j < 4; ++j) acc[nt][j] = 0.f;

        uint32_t Ah[4], Al[4];
        const uint32_t aoff = ((uint32_t)(wid*16 + (lane & 15)) * PAST + ((lane & 16) ? 8u : 0u)) * 2u;
        ldsm4(Ah, paHi + aoff);
        ldsm4(Al, paLo + aoff);
        const uint32_t boff = ((uint32_t)(lane & 7) * PAST + ((lane & 8) ? 8u : 0u)) * 2u;
        #pragma unroll
        for (int nt = 0; nt < 12; ++nt) {
            uint32_t Bh[2], Bl[2];
            uint32_t bb = boff + (uint32_t)(nt*8*PAST*2);
            ldsm2(Bh, pwHi + bb);
            ldsm2(Bl, pwLo + bb);
            mma_bf16(acc[nt], Ah, Bh);
            mma_bf16(acc[nt], Ah, Bl);
            mma_bf16(acc[nt], Al, Bh);
        }

        // epilogue -> fp32 staging at stride 100 (aliases A region; A reads done)
        float* stg = (float*)(smem + SP_A);
        #pragma unroll
        for (int nt = 0; nt < 12; ++nt) {
            int col = nt*8 + cb0;
            float bb0 = __ldg(bo + col), bb1 = __ldg(bo + col + 1);
            stg[r0*100 + col]        = acc[nt][0] + bb0;
            stg[r0*100 + col + 1]    = acc[nt][1] + bb1;
            stg[(r0+8)*100 + col]    = acc[nt][2] + bb0;
            stg[(r0+8)*100 + col+1]  = acc[nt][3] + bb1;
        }
    }
    __syncthreads();

    // coalesced scatter to g_buf
    {
        const float* stg = (const float*)(smem + SP_A);
        #pragma unroll
        for (int r = 0; r < 48; ++r) {
            int idx = r*256 + tid;          // < 12288
            int tok = idx / C_, c = idx - tok*C_;
            g_buf[gofs[tok] + c] = stg[tok*100 + c];
        }
    }
}

// ---------------------------------------------------------------------------
// Kernel 2: temporal MHA (in-place on g_buf). Block = (b,h, 8-wide w strip),
// 64 token slots = 8 positions x 8 timesteps.  (unchanged from round 5)
// ---------------------------------------------------------------------------
__global__ __launch_bounds__(256, 3) void k_temporal(
    const float* __restrict__ Wq, const float* __restrict__ bq,
    const float* __restrict__ Wk, const float* __restrict__ bk,
    const float* __restrict__ Wv, const float* __restrict__ bv,
    const float* __restrict__ Wo, const float* __restrict__ bo)
{
    extern __shared__ float sm[];
    float* xin = sm;                    // 64*100  slot s = p*8 + t
    float* qkv = xin + NT_*PAD_;        // 64*48
    float* Wt  = qkv + NT_*48;          // 48*100 (reused as oT)
    float* WoS = Wt + 48*PAD_;          // 16*96

    const int tid = threadIdx.x;
    const int blk = blockIdx.x;
    const int wp = blk % (W_/8);
    const int h  = (blk / (W_/8)) % H_;
    const int b  = blk / ((W_/8)*H_);
    const int w0 = wp*8;
    const int base0   = (((b*T_)*H_ + h)*W_ + w0)*C_;
    const int tstride = H_*W_*C_;

    #pragma unroll
    for (int r = 0; r < 18; ++r) {
        int idx = r*256 + tid;
        int j = idx / 96, c = idx - j*96;
        int which = j >> 4, hk = j & 15;
        const float* Wm = (which==0) ? Wq : ((which==1) ? Wk : Wv);
        Wt[j*PAD_ + c] = Wm[c*16 + hk];
    }
    #pragma unroll
    for (int r = 0; r < 6; ++r) WoS[r*256+tid] = Wo[r*256+tid];

    #pragma unroll
    for (int r = 0; r < 24; ++r) {
        int idx = r*256 + tid;
        int t = idx / 768; int rem = idx - t*768;
        int p = rem / C_;  int c = rem - p*C_;
        xin[(p*8+t)*PAD_ + c] = g_buf[base0 + t*tstride + rem];
    }
    __syncthreads();

    {
        const int tx = tid & 15;
        const int ty = tid >> 4;
        float acc[4][3];
        #pragma unroll
        for (int tn = 0; tn < 3; ++tn) {
            int j = tx*3 + tn;
            int which = j >> 4, hk = j & 15;
            float bias = (which==0) ? bq[hk] : ((which==1) ? bk[hk] : bv[hk]);
            #pragma unroll
            for (int tm = 0; tm < 4; ++tm) acc[tm][tn] = bias;
        }
        #pragma unroll 6
        for (int c = 0; c < C_; c += 4) {
            float4 a[4], w[3];
            #pragma unroll
            for (int tm = 0; tm < 4; ++tm) a[tm] = *(const float4*)(xin + (ty*4+tm)*PAD_ + c);
            #pragma unroll
            for (int tn = 0; tn < 3; ++tn) w[tn] = *(const float4*)(Wt + (tx*3+tn)*PAD_ + c);
            #pragma unroll
            for (int tm = 0; tm < 4; ++tm)
                #pragma unroll
                for (int tn = 0; tn < 3; ++tn) {
                    acc[tm][tn] = fmaf(a[tm].x, w[tn].x, acc[tm][tn]);
                    acc[tm][tn] = fmaf(a[tm].y, w[tn].y, acc[tm][tn]);
                    acc[tm][tn] = fmaf(a[tm].z, w[tn].z, acc[tm][tn]);
                    acc[tm][tn] = fmaf(a[tm].w, w[tn].w, acc[tm][tn]);
                }
        }
        #pragma unroll
        for (int tm = 0; tm < 4; ++tm)
            #pragma unroll
            for (int tn = 0; tn < 3; ++tn)
                qkv[(ty*4+tm)*48 + tx*3 + tn] = acc[tm][tn];
    }
    __syncthreads();

    float* oT = Wt;
    if (tid < 128) {
        const int p  = tid >> 4;
        const int hh = (tid >> 3) & 1;
        const int n  = tid & 7;
        const int sb = p*8;
        float4 q0 = *(const float4*)(qkv + (sb+n)*48 + hh*8);
        float4 q1 = *(const float4*)(qkv + (sb+n)*48 + hh*8 + 4);
        q0.x *= SCALE_; q0.y *= SCALE_; q0.z *= SCALE_; q0.w *= SCALE_;
        q1.x *= SCALE_; q1.y *= SCALE_; q1.z *= SCALE_; q1.w *= SCALE_;
        float sc[8]; float mx = -1e30f;
        #pragma unroll
        for (int m = 0; m < 8; ++m) {
            const float4 k0 = *(const float4*)(qkv + (sb+m)*48 + 16 + hh*8);
            const float4 k1 = *(const float4*)(qkv + (sb+m)*48 + 20 + hh*8);
            float s = q0.x*k0.x + q0.y*k0.y + q0.z*k0.z + q0.w*k0.w
                    + q1.x*k1.x + q1.y*k1.y + q1.z*k1.z + q1.w*k1.w;
            sc[m] = s; mx = fmaxf(mx, s);
        }
        float sum = 0.f;
        #pragma unroll
        for (int m = 0; m < 8; ++m) { sc[m] = __expf(sc[m]-mx); sum += sc[m]; }
        float inv = 1.0f/sum;
        float o[8] = {0.f,0.f,0.f,0.f,0.f,0.f,0.f,0.f};
        #pragma unroll
        for (int m = 0; m < 8; ++m) {
            const float4 v0 = *(const float4*)(qkv + (sb+m)*48 + 32 + hh*8);
            const float4 v1 = *(const float4*)(qkv + (sb+m)*48 + 36 + hh*8);
            o[0] = fmaf(sc[m], v0.x, o[0]);
            o[1] = fmaf(sc[m], v0.y, o[1]);
            o[2] = fmaf(sc[m], v0.z, o[2]);
            o[3] = fmaf(sc[m], v0.w, o[3]);
            o[4] = fmaf(sc[m], v1.x, o[4]);
            o[5] = fmaf(sc[m], v1.y, o[5]);
            o[6] = fmaf(sc[m], v1.z, o[6]);
            o[7] = fmaf(sc[m], v1.w, o[7]);
        }
        __syncthreads();   // qkv reads done; oT overwrites Wt region
        #pragma unroll
        for (int i = 0; i < 8; ++i) oT[(hh*8+i)*64 + (sb+n)] = o[i]*inv;
    } else {
        __syncthreads();
    }
    __syncthreads();

    {
        const int tx = tid & 15;
        const int ty = tid >> 4;
        float acc[4][6];
        #pragma unroll
        for (int tn = 0; tn < 6; ++tn) {
            float bias = bo[tx*6+tn];
            #pragma unroll
            for (int tm = 0; tm < 4; ++tm) acc[tm][tn] = bias;
        }
        #pragma unroll
        for (int hk = 0; hk < 16; ++hk) {
            float4 av = *(const float4*)(oT + hk*64 + ty*4);
            float a[4] = {av.x, av.y, av.z, av.w};
            float w[6];
            #pragma unroll
            for (int tn = 0; tn < 6; ++tn) w[tn] = WoS[hk*96 + tx*6 + tn];
            #pragma unroll
            for (int tm = 0; tm < 4; ++tm)
                #pragma unroll
                for (int tn = 0; tn < 6; ++tn)
                    acc[tm][tn] = fmaf(a[tm], w[tn], acc[tm][tn]);
        }
        #pragma unroll
        for (int tm = 0; tm < 4; ++tm)
            #pragma unroll
            for (int tn = 0; tn < 6; ++tn)
                xin[(ty*4+tm)*PAD_ + tx*6 + tn] = acc[tm][tn];
    }
    __syncthreads();
    #pragma unroll
    for (int r = 0; r < 24; ++r) {
        int idx = r*256 + tid;
        int t = idx / 768; int rem = idx - t*768;
        int p = rem / C_;  int c = rem - p*C_;
        g_buf[base0 + t*tstride + rem] = xin[(p*8+t)*PAD_ + c];
    }
}

// smem byte offsets for k_mlp_mma
#define MO_AHI   0
#define MO_ALO   (MO_AHI + 128*AST*2)        // 26624
#define MO_WHI   (MO_ALO + 128*AST*2)        // 53248
#define MO_WLO   (MO_WHI + 96*AST*2)         // 73216
#define MO_BIAS  (MO_WLO + 96*AST*2)         // 93184
#define MO_TOTAL (MO_BIAS + 4*96*4)          // 94720

// shared 128x96 GEMM: D(acc) += Ahi*Whi + Ahi*Wlo + Alo*Whi
__device__ __forceinline__ void gemm_128x96(
    uint32_t aHi, uint32_t aLo, uint32_t bHi, uint32_t bLo,
    int wid, int lane, float acc[12][4])
{
    const uint32_t aoff = ((uint32_t)(wid*16 + (lane & 15)) * AST + ((lane & 16) ? 8u : 0u)) * 2u;
    const uint32_t boff = ((uint32_t)(lane & 7) * AST + ((lane & 8) ? 8u : 0u)) * 2u;
    #pragma unroll
    for (int kb = 0; kb < 6; ++kb) {
        uint32_t Ah[4], Al[4];
        ldsm4(Ah, aHi + aoff + kb*32u);
        ldsm4(Al, aLo + aoff + kb*32u);
        #pragma unroll
        for (int nt = 0; nt < 12; ++nt) {
            uint32_t Bh[2], Bl[2];
            uint32_t bb = boff + (uint32_t)(nt*8*AST*2) + kb*32u;
            ldsm2(Bh, bHi + bb);
            ldsm2(Bl, bLo + bb);
            mma_bf16(acc[nt], Ah, Bh);
            mma_bf16(acc[nt], Ah, Bl);
            mma_bf16(acc[nt], Al, Bh);
        }
    }
}

// ---------------------------------------------------------------------------
// Kernel 3: LN2 + MLP via mma.sync bf16 hi/lo (unchanged from round 5)
// ---------------------------------------------------------------------------
__global__ __launch_bounds__(256, 2) void k_mlp_mma(
    const float* __restrict__ g2, const float* __restrict__ b2,
    const float* __restrict__ W1, const float* __restrict__ b1m,
    const float* __restrict__ W2, const float* __restrict__ b2m,
    float* __restrict__ out)
{
    extern __shared__ char smem[];
    const int tid  = threadIdx.x;
    const int wid  = tid >> 5;
    const int lane = tid & 31;
    const int gbase = blockIdx.x * 128 * C_;

    __nv_bfloat16* sAhi = (__nv_bfloat16*)(smem + MO_AHI);
    __nv_bfloat16* sAlo = (__nv_bfloat16*)(smem + MO_ALO);
    __nv_bfloat16* sWhi = (__nv_bfloat16*)(smem + MO_WHI);
    __nv_bfloat16* sWlo = (__nv_bfloat16*)(smem + MO_WLO);
    float* sG2  = (float*)(smem + MO_BIAS);
    float* sB2  = sG2 + 96;
    float* sB1M = sG2 + 192;
    float* sB2M = sG2 + 288;

    const uint32_t aHi = smem_u32(sAhi);
    const uint32_t aLo = smem_u32(sAlo);
    const uint32_t wHi = smem_u32(sWhi);
    const uint32_t wLo = smem_u32(sWlo);

    if (tid < 96) {
        sG2[tid]  = g2[tid];
        sB2[tid]  = b2[tid];
        sB1M[tid] = b1m[tid];
        sB2M[tid] = b2m[tid];
    }
    #pragma unroll 4
    for (int i = tid; i < C_*C_; i += 256) {
        int k = i / C_, n = i - k*C_;
        __nv_bfloat16 hi, lo;
        split_bf16(W1[i], hi, lo);
        sWhi[n*AST + k] = hi;
        sWlo[n*AST + k] = lo;
    }

    {
        const float* xin = g_buf + gbase;
        #pragma unroll
        for (int bb = 0; bb < 2; ++bb) {
            float v[8][3];
            #pragma unroll
            for (int i = 0; i < 8; ++i) {
                int tok = wid*16 + bb*8 + i;
                const float* row = xin + tok*C_ + lane;
                v[i][0] = row[0]; v[i][1] = row[32]; v[i][2] = row[64];
            }
            #pragma unroll
            for (int i = 0; i < 8; ++i) {
                int tok = wid*16 + bb*8 + i;
                float s = v[i][0] + v[i][1] + v[i][2];
                float q = v[i][0]*v[i][0];
                q = fmaf(v[i][1], v[i][1], q);
                q = fmaf(v[i][2], v[i][2], q);
                #pragma unroll
                for (int o = 16; o > 0; o >>= 1) {
                    s += __shfl_xor_sync(0xffffffffu, s, o);
                    q += __shfl_xor_sync(0xffffffffu, q, o);
                }
                float mu = s * (1.0f/C_);
                float var = q * (1.0f/C_) - mu*mu;
                float rs = rsqrtf(var + EPS_);
                #pragma unroll
                for (int j = 0; j < 3; ++j) {
                    int c = lane + 32*j;
                    float y = (v[i][j] - mu) * rs * sG2[c] + sB2[c];
                    __nv_bfloat16 hi, lo;
                    split_bf16(y, hi, lo);
                    sAhi[tok*AST + c] = hi;
                    sAlo[tok*AST + c] = lo;
                }
            }
        }
    }
    __syncthreads();

    const int r0  = wid*16 + (lane >> 2);
    const int cb0 = (lane & 3) * 2;

    float acc[12][4];
    #pragma unroll
    for (int nt = 0; nt < 12; ++nt)
        #pragma unroll
        for (int j = 0; j < 4; ++j) acc[nt][j] = 0.f;
    gemm_128x96(aHi, aLo, wHi, wLo, wid, lane, acc);
    __syncthreads();

    #pragma unroll
    for (int nt = 0; nt < 12; ++nt) {
        int col = nt*8 + cb0;
        float h00 = fmaxf(acc[nt][0] + sB1M[col],     0.f);
        float h01 = fmaxf(acc[nt][1] + sB1M[col + 1], 0.f);
        float h10 = fmaxf(acc[nt][2] + sB1M[col],     0.f);
        float h11 = fmaxf(acc[nt][3] + sB1M[col + 1], 0.f);
        __nv_bfloat16 hi, lo;
        split_bf16(h00, hi, lo); sAhi[r0*AST + col]       = hi; sAlo[r0*AST + col]       = lo;
        split_bf16(h01, hi, lo); sAhi[r0*AST + col + 1]   = hi; sAlo[r0*AST + col + 1]   = lo;
        split_bf16(h10, hi, lo); sAhi[(r0+8)*AST + col]   = hi; sAlo[(r0+8)*AST + col]   = lo;
        split_bf16(h11, hi, lo); sAhi[(r0+8)*AST + col+1] = hi; sAlo[(r0+8)*AST + col+1] = lo;
    }
    #pragma unroll 4
    for (int i = tid; i < C_*C_; i += 256) {
        int k = i / C_, n = i - k*C_;
        __nv_bfloat16 hi, lo;
        split_bf16(W2[i], hi, lo);
        sWhi[n*AST + k] = hi;
        sWlo[n*AST + k] = lo;
    }
    __syncthreads();

    #pragma unroll
    for (int nt = 0; nt < 12; ++nt)
        #pragma unroll
        for (int j = 0; j < 4; ++j) acc[nt][j] = 0.f;
    gemm_128x96(aHi, aLo, wHi, wLo, wid, lane, acc);
    __syncthreads();

    float* stg = (float*)(smem + MO_AHI);
    #pragma unroll
    for (int nt = 0; nt < 12; ++nt) {
        int col = nt*8 + cb0;
        stg[r0*97 + col]       = fmaxf(acc[nt][0] + sB2M[col],     0.f);
        stg[r0*97 + col + 1]   = fmaxf(acc[nt][1] + sB2M[col + 1], 0.f);
        stg[(r0+8)*97 + col]   = fmaxf(acc[nt][2] + sB2M[col],     0.f);
        stg[(r0+8)*97 + col+1] = fmaxf(acc[nt][3] + sB2M[col + 1], 0.f);
    }
    __syncthreads();
    #pragma unroll
    for (int i = 0; i < 48; ++i) {
        int idx = i*256 + tid;
        int tok = idx / C_, c = idx - tok*C_;
        out[gbase + idx] = stg[tok*97 + c];
    }
}

// ---------------------------------------------------------------------------
extern "C" void kernel_launch(void* const* d_in, const int* in_sizes, int n_in,
                              void* d_out, int out_size)
{
    const float* x   = (const float*)d_in[0];
    const float* g1  = (const float*)d_in[1];
    const float* b1  = (const float*)d_in[2];
    const float* g2  = (const float*)d_in[3];
    const float* b2  = (const float*)d_in[4];
    const float* Wq  = (const float*)d_in[5];
    const float* bq  = (const float*)d_in[6];
    const float* Wk  = (const float*)d_in[7];
    const float* bk  = (const float*)d_in[8];
    const float* Wv  = (const float*)d_in[9];
    const float* bv  = (const float*)d_in[10];
    const float* Wo  = (const float*)d_in[11];
    const float* bo  = (const float*)d_in[12];
    const float* W1  = (const float*)d_in[13];
    const float* b1m = (const float*)d_in[14];
    const float* W2  = (const float*)d_in[15];
    const float* b2m = (const float*)d_in[16];
    float* out = (float*)d_out;

    const int smem2 = (NT_*PAD_ + NT_*48 + 48*PAD_ + 16*C_) * sizeof(float);  // 63232

    cudaFuncSetAttribute(k_spatial_mma, cudaFuncAttributeMaxDynamicSharedMemorySize, SP_TOTAL);
    cudaFuncSetAttribute(k_temporal,    cudaFuncAttributeMaxDynamicSharedMemorySize, smem2);
    cudaFuncSetAttribute(k_mlp_mma,     cudaFuncAttributeMaxDynamicSharedMemorySize, MO_TOTAL);

    k_spatial_mma<<<B_*T_*(NWH_*NWW_/2), 256, SP_TOTAL>>>(x, g1, b1, Wq, bq, Wk, bk, Wv, bv, Wo, bo);
    k_temporal<<<B_*H_*(W_/8), 256, smem2>>>(Wq, bq, Wk, bk, Wv, bv, Wo, bo);
    k_mlp_mma<<<(B_*T_*H_*W_)/128, 256, MO_TOTAL>>>(g2, b2, W1, b1m, W2, b2m, out);
}